// round 1
// baseline (speedup 1.0000x reference)
#include <cuda_runtime.h>

#define Bdim 32
#define Cdim 32
#define Ndim 160
#define Ldim 160
#define NL (Ndim*Ldim)          // 25600
#define BC (Bdim*Cdim)          // 1024
#define ALPHA 0.05f
#define OMA 0.95f               // 1 - ALPHA

// ---- scratch (allocation-free rule: __device__ globals) ----
__device__ float g_A1[Ndim*Ndim];
__device__ float g_A2[Ndim*Ndim];
__device__ float g_h1a[(size_t)BC*NL];
__device__ float g_h1b[(size_t)BC*NL];
__device__ float g_u2 [(size_t)BC*NL];
__device__ float g_embed[(size_t)BC*NL];
__device__ float g_pool [(size_t)BC*NL];   // becomes s after softmax (in place)
__device__ float g_t    [(size_t)BC*NL];   // s @ a

// ============================================================
// K1: row-normalized (a+I) and (a^T+I)
// ============================================================
__global__ void k_norm_adj(const float* __restrict__ a) {
    int v = blockIdx.x;          // row
    int t = threadIdx.x;         // col, 160 threads
    __shared__ float s1[Ndim], s2[Ndim];
    __shared__ float r1, r2;
    float av = a[v*Ndim + t];    // row v of a
    float aw = a[t*Ndim + v];    // row v of a^T
    s1[t] = av; s2[t] = aw;
    __syncthreads();
    if (t == 0) {
        float x1 = 0.f, x2 = 0.f;
        for (int i = 0; i < Ndim; i++) { x1 += s1[i]; x2 += s2[i]; }
        r1 = x1 + 1.f; r2 = x2 + 1.f;   // +1 for identity diagonal
    }
    __syncthreads();
    float diag = (t == v) ? 1.f : 0.f;
    g_A1[v*Ndim + t] = (av + diag) / r1;
    g_A2[v*Ndim + t] = (aw + diag) / r2;
}

// ============================================================
// K2: h1a = a*x + (1-a)*A1@x ; h1b = a*x + (1-a)*A2@x   (fused, shares x tile)
// ============================================================
__global__ void k_hop1(const float* __restrict__ x) {
    int bc = blockIdx.z;
    int bi = blockIdx.y, bj = blockIdx.x;
    __shared__ float As1[32][32], As2[32][32], Bs[32][33];
    int tx = threadIdx.x, ty = threadIdx.y;
    int tid = ty*16 + tx;
    const float* xb = x + (size_t)bc*NL;
    float acc1[2][2] = {}, acc2[2][2] = {};
    for (int kt = 0; kt < 5; kt++) {
        #pragma unroll
        for (int idx = tid; idx < 1024; idx += 256) {
            int r = idx >> 5, c = idx & 31;
            As1[r][c] = g_A1[(bi*32+r)*Ndim + kt*32 + c];
            As2[r][c] = g_A2[(bi*32+r)*Ndim + kt*32 + c];
            Bs [r][c] = xb[(kt*32+r)*Ldim + bj*32 + c];
        }
        __syncthreads();
        #pragma unroll
        for (int k = 0; k < 32; k++) {
            float b0 = Bs[k][tx], b1 = Bs[k][tx+16];
            float a10 = As1[ty][k], a11 = As1[ty+16][k];
            float a20 = As2[ty][k], a21 = As2[ty+16][k];
            acc1[0][0] += a10*b0; acc1[0][1] += a10*b1;
            acc1[1][0] += a11*b0; acc1[1][1] += a11*b1;
            acc2[0][0] += a20*b0; acc2[0][1] += a20*b1;
            acc2[1][0] += a21*b0; acc2[1][1] += a21*b1;
        }
        __syncthreads();
    }
    #pragma unroll
    for (int i = 0; i < 2; i++)
    #pragma unroll
    for (int j = 0; j < 2; j++) {
        int v = bi*32 + ty + i*16, l = bj*32 + tx + j*16;
        float xv = xb[v*Ldim + l];
        size_t o = (size_t)bc*NL + v*Ldim + l;
        g_h1a[o] = ALPHA*xv + OMA*acc1[i][j];
        g_h1b[o] = ALPHA*xv + OMA*acc2[i][j];
    }
}

// ============================================================
// K3: u2 = h2a + h2b = 2a*x + (1-a)*(A1@h1a + A2@h1b)   (fused)
// ============================================================
__global__ void k_hop2(const float* __restrict__ x) {
    int bc = blockIdx.z;
    int bi = blockIdx.y, bj = blockIdx.x;
    __shared__ float As1[32][32], As2[32][32], B1s[32][33], B2s[32][33];
    int tx = threadIdx.x, ty = threadIdx.y;
    int tid = ty*16 + tx;
    const float* xb = x + (size_t)bc*NL;
    const float* h1a = g_h1a + (size_t)bc*NL;
    const float* h1b = g_h1b + (size_t)bc*NL;
    float acc[2][2] = {};
    for (int kt = 0; kt < 5; kt++) {
        #pragma unroll
        for (int idx = tid; idx < 1024; idx += 256) {
            int r = idx >> 5, c = idx & 31;
            As1[r][c] = g_A1[(bi*32+r)*Ndim + kt*32 + c];
            As2[r][c] = g_A2[(bi*32+r)*Ndim + kt*32 + c];
            B1s[r][c] = h1a[(kt*32+r)*Ldim + bj*32 + c];
            B2s[r][c] = h1b[(kt*32+r)*Ldim + bj*32 + c];
        }
        __syncthreads();
        #pragma unroll
        for (int k = 0; k < 32; k++) {
            float b10 = B1s[k][tx], b11 = B1s[k][tx+16];
            float b20 = B2s[k][tx], b21 = B2s[k][tx+16];
            float a10 = As1[ty][k], a11 = As1[ty+16][k];
            float a20 = As2[ty][k], a21 = As2[ty+16][k];
            acc[0][0] += a10*b10 + a20*b20;
            acc[0][1] += a10*b11 + a20*b21;
            acc[1][0] += a11*b10 + a21*b20;
            acc[1][1] += a11*b11 + a21*b21;
        }
        __syncthreads();
    }
    #pragma unroll
    for (int i = 0; i < 2; i++)
    #pragma unroll
    for (int j = 0; j < 2; j++) {
        int v = bi*32 + ty + i*16, l = bj*32 + tx + j*16;
        float xv = xb[v*Ldim + l];
        g_u2[(size_t)bc*NL + v*Ldim + l] = 2.f*ALPHA*xv + OMA*acc[i][j];
    }
}

// ============================================================
// K4: channel mix. out64[o,p] = sum_k W[o,k]*H[k,p]
//   W rows 0..31 = We (embed), 32..63 = Wp (pool). Hop-0 columns scaled x2.
//   H rows: [x(32); h1a+h1b(32); u2(32)]. Bias 2*be / 2*bp.
// ============================================================
__global__ void k_mix(const float* __restrict__ x,
                      const float* __restrict__ We, const float* __restrict__ be,
                      const float* __restrict__ Wp, const float* __restrict__ bp) {
    int b  = blockIdx.y;
    int p0 = blockIdx.x * 64;
    int tid = threadIdx.x;            // 256
    int tx = tid & 15, ty = tid >> 4;
    __shared__ float Ws[64][33];
    __shared__ float Hs[32][64];
    float acc[4][4] = {};
    for (int kc = 0; kc < 3; kc++) {
        #pragma unroll
        for (int idx = tid; idx < 2048; idx += 256) {
            int o = idx >> 5, k = idx & 31;
            float w = (o < 32) ? We[o*96 + kc*32 + k] : Wp[(o-32)*96 + kc*32 + k];
            if (kc == 0) w *= 2.f;
            Ws[o][k] = w;
        }
        #pragma unroll
        for (int idx = tid; idx < 2048; idx += 256) {
            int k = idx >> 6, p = idx & 63;
            size_t off = (size_t)(b*32 + k)*NL + p0 + p;
            float h;
            if      (kc == 0) h = x[off];
            else if (kc == 1) h = g_h1a[off] + g_h1b[off];
            else              h = g_u2[off];
            Hs[k][p] = h;
        }
        __syncthreads();
        #pragma unroll
        for (int k = 0; k < 32; k++) {
            float4 hv = reinterpret_cast<const float4*>(&Hs[k][0])[tx];
            float wv0 = Ws[ty*4+0][k], wv1 = Ws[ty*4+1][k];
            float wv2 = Ws[ty*4+2][k], wv3 = Ws[ty*4+3][k];
            acc[0][0]+=wv0*hv.x; acc[0][1]+=wv0*hv.y; acc[0][2]+=wv0*hv.z; acc[0][3]+=wv0*hv.w;
            acc[1][0]+=wv1*hv.x; acc[1][1]+=wv1*hv.y; acc[1][2]+=wv1*hv.z; acc[1][3]+=wv1*hv.w;
            acc[2][0]+=wv2*hv.x; acc[2][1]+=wv2*hv.y; acc[2][2]+=wv2*hv.z; acc[2][3]+=wv2*hv.w;
            acc[3][0]+=wv3*hv.x; acc[3][1]+=wv3*hv.y; acc[3][2]+=wv3*hv.z; acc[3][3]+=wv3*hv.w;
        }
        __syncthreads();
    }
    #pragma unroll
    for (int i = 0; i < 4; i++) {
        int o = ty*4 + i;
        float bias = (o < 32) ? 2.f*be[o] : 2.f*bp[o-32];
        float4 v = make_float4(acc[i][0]+bias, acc[i][1]+bias, acc[i][2]+bias, acc[i][3]+bias);
        size_t off;
        if (o < 32) off = (size_t)(b*32 + o)*NL + p0 + tx*4;
        else        off = (size_t)(b*32 + (o-32))*NL + p0 + tx*4;
        float* dst = (o < 32) ? g_embed : g_pool;
        reinterpret_cast<float4*>(dst + off)[0] = v;
    }
}

// ============================================================
// K5: in-place softmax of g_pool over node axis (stride L per step)
// ============================================================
__global__ void k_softmax() {
    int bc = blockIdx.x;              // 1024
    int l = threadIdx.x;              // 160
    float* p = g_pool + (size_t)bc*NL;
    float m = -3.4e38f, d = 0.f;
    for (int n = 0; n < Ndim; n++) {
        float v = p[n*Ldim + l];
        float m2 = fmaxf(m, v);
        d = d * __expf(m - m2) + __expf(v - m2);
        m = m2;
    }
    float inv = 1.f / d;
    for (int n = 0; n < Ndim; n++) {
        p[n*Ldim + l] = __expf(p[n*Ldim + l] - m) * inv;
    }
}

// ============================================================
// Generic batched 160x160x160 GEMM, 32x32 tiles, 2x2 micro.
// TA=true: C = A^T * B (A stored [K,M]); else C = A * B.
// Per-batch strides sA/sB/sC (sB=0 shares B across batches).
// ============================================================
template<bool TA>
__global__ void k_bgemm(const float* __restrict__ A, long sA,
                        const float* __restrict__ Bm, long sB,
                        float* __restrict__ Cm, long sC) {
    int bc = blockIdx.z;
    const float* Ab = A  + (size_t)bc*sA;
    const float* Bb = Bm + (size_t)bc*sB;
    float*       Cb = Cm + (size_t)bc*sC;
    __shared__ float As[32][33], Bs[32][33];
    int tx = threadIdx.x, ty = threadIdx.y;
    int tid = ty*16 + tx;
    int bi = blockIdx.y, bj = blockIdx.x;
    float acc[2][2] = {};
    for (int kt = 0; kt < 5; kt++) {
        #pragma unroll
        for (int idx = tid; idx < 1024; idx += 256) {
            int r = idx >> 5, c = idx & 31;
            if (TA) As[r][c] = Ab[(kt*32+r)*Ndim + bi*32 + c];   // As[k][m]
            else    As[c][r] = Ab[(bi*32+r)*Ndim + kt*32 + c];   // transpose to As[k][m]
            Bs[r][c] = Bb[(kt*32+r)*Ndim + bj*32 + c];
        }
        __syncthreads();
        #pragma unroll
        for (int k = 0; k < 32; k++) {
            float a0 = As[k][ty], a1 = As[k][ty+16];
            float b0 = Bs[k][tx], b1 = Bs[k][tx+16];
            acc[0][0] += a0*b0; acc[0][1] += a0*b1;
            acc[1][0] += a1*b0; acc[1][1] += a1*b1;
        }
        __syncthreads();
    }
    #pragma unroll
    for (int i = 0; i < 2; i++)
    #pragma unroll
    for (int j = 0; j < 2; j++)
        Cb[(bi*32+ty+i*16)*Ldim + bj*32+tx+j*16] = acc[i][j];
}

// ============================================================
extern "C" void kernel_launch(void* const* d_in, const int* in_sizes, int n_in,
                              void* d_out, int out_size) {
    const float* x  = (const float*)d_in[0];
    const float* a  = (const float*)d_in[1];
    const float* We = (const float*)d_in[2];
    const float* be = (const float*)d_in[3];
    const float* Wp = (const float*)d_in[4];
    const float* bp = (const float*)d_in[5];
    float* out  = (float*)d_out;
    float* xnew = out;
    float* anew = out + (size_t)BC*NL;

    void *p_pool, *p_embed, *p_t;
    cudaGetSymbolAddress(&p_pool,  g_pool);
    cudaGetSymbolAddress(&p_embed, g_embed);
    cudaGetSymbolAddress(&p_t,     g_t);

    dim3 g55(5, 5, BC), b16(16, 16);

    k_norm_adj<<<Ndim, Ndim>>>(a);
    k_hop1<<<g55, b16>>>(x);
    k_hop2<<<g55, b16>>>(x);
    k_mix<<<dim3(NL/64, Bdim), 256>>>(x, We, be, Wp, bp);
    k_softmax<<<BC, Ldim>>>();
    // x_new = s^T @ embed
    k_bgemm<true ><<<g55, b16>>>((const float*)p_pool, NL, (const float*)p_embed, NL, xnew, NL);
    // t = s @ a  (a shared across batches)
    k_bgemm<false><<<g55, b16>>>((const float*)p_pool, NL, a, 0, (float*)p_t, NL);
    // a_new = t @ s
    k_bgemm<false><<<g55, b16>>>((const float*)p_t, NL, (const float*)p_pool, NL, anew, NL);
}

// round 2
// speedup vs baseline: 2.2963x; 2.2963x over previous
#include <cuda_runtime.h>

#define Bdim 32
#define Cdim 32
#define Ndim 160
#define Ldim 160
#define NL (Ndim*Ldim)          // 25600
#define BC (Bdim*Cdim)          // 1024
#define ALPHA 0.05f
#define OMA 0.95f               // 1 - ALPHA

// ---- scratch (allocation-free rule: __device__ globals) ----
__device__ float g_A1[Ndim*Ndim];
__device__ float g_A2[Ndim*Ndim];
__device__ float g_M1[Ndim*Ndim];          // (1-a)(A1+A2)
__device__ float g_M2[Ndim*Ndim];          // a(1-a)(A1+A2) + (1-a)^2(A1^2+A2^2)
__device__ float g_y1[(size_t)BC*NL];      // M1 @ x
__device__ float g_y2[(size_t)BC*NL];      // M2 @ x
__device__ float g_embed[(size_t)BC*NL];
__device__ float g_pool [(size_t)BC*NL];   // becomes s after softmax
__device__ float g_t    [(size_t)BC*NL];   // s @ a

// ============================================================
// K1: row-normalized (a+I) and (a^T+I)
// ============================================================
__global__ void k_norm_adj(const float* __restrict__ a) {
    int v = blockIdx.x;
    int t = threadIdx.x;
    __shared__ float s1[Ndim], s2[Ndim];
    __shared__ float r1, r2;
    float av = a[v*Ndim + t];
    float aw = a[t*Ndim + v];
    s1[t] = av; s2[t] = aw;
    __syncthreads();
    if (t == 0) {
        float x1 = 0.f, x2 = 0.f;
        for (int i = 0; i < Ndim; i++) { x1 += s1[i]; x2 += s2[i]; }
        r1 = x1 + 1.f; r2 = x2 + 1.f;
    }
    __syncthreads();
    float diag = (t == v) ? 1.f : 0.f;
    g_A1[v*Ndim + t] = (av + diag) / r1;
    g_A2[v*Ndim + t] = (aw + diag) / r2;
}

// ============================================================
// K2: M1 = (1-a)(A1+A2), M2 = a(1-a)(A1+A2) + (1-a)^2 (A1@A1 + A2@A2)
// dual GEMM, 32x32 tile, 4x4 micro, 64 threads
// ============================================================
__global__ void k_prep() {
    __shared__ float As1[32][36], As2[32][36], Bs1[32][36], Bs2[32][36];
    int tid = threadIdx.x;
    int tx = tid & 7, ty = tid >> 3;
    int bi = blockIdx.y, bj = blockIdx.x;
    float c1[4][4] = {}, c2[4][4] = {};
    for (int kt = 0; kt < 5; kt++) {
        #pragma unroll
        for (int it = 0; it < 4; it++) {
            int g = tid + it*64;
            // transposed A loads: As[k][m]
            int m = g >> 3, k4 = g & 7;
            float4 v1 = *(const float4*)&g_A1[(bi*32+m)*Ndim + kt*32 + k4*4];
            float4 v2 = *(const float4*)&g_A2[(bi*32+m)*Ndim + kt*32 + k4*4];
            As1[k4*4+0][m] = v1.x; As1[k4*4+1][m] = v1.y;
            As1[k4*4+2][m] = v1.z; As1[k4*4+3][m] = v1.w;
            As2[k4*4+0][m] = v2.x; As2[k4*4+1][m] = v2.y;
            As2[k4*4+2][m] = v2.z; As2[k4*4+3][m] = v2.w;
            // direct B loads
            int r = g >> 3, c4 = g & 7;
            *(float4*)&Bs1[r][c4*4] = *(const float4*)&g_A1[(kt*32+r)*Ndim + bj*32 + c4*4];
            *(float4*)&Bs2[r][c4*4] = *(const float4*)&g_A2[(kt*32+r)*Ndim + bj*32 + c4*4];
        }
        __syncthreads();
        #pragma unroll
        for (int k = 0; k < 32; k++) {
            float4 a1 = *(const float4*)&As1[k][ty*4];
            float4 a2 = *(const float4*)&As2[k][ty*4];
            float4 b1 = *(const float4*)&Bs1[k][tx*4];
            float4 b2 = *(const float4*)&Bs2[k][tx*4];
            float aa1[4] = {a1.x,a1.y,a1.z,a1.w}, aa2[4] = {a2.x,a2.y,a2.z,a2.w};
            float bb1[4] = {b1.x,b1.y,b1.z,b1.w}, bb2[4] = {b2.x,b2.y,b2.z,b2.w};
            #pragma unroll
            for (int i = 0; i < 4; i++)
            #pragma unroll
            for (int j = 0; j < 4; j++) {
                c1[i][j] += aa1[i]*bb1[j];
                c2[i][j] += aa2[i]*bb2[j];
            }
        }
        __syncthreads();
    }
    #pragma unroll
    for (int i = 0; i < 4; i++) {
        int row = bi*32 + ty*4 + i;
        int col = bj*32 + tx*4;
        float4 a1 = *(const float4*)&g_A1[row*Ndim + col];
        float4 a2 = *(const float4*)&g_A2[row*Ndim + col];
        float s0 = a1.x + a2.x, s1v = a1.y + a2.y, s2v = a1.z + a2.z, s3 = a1.w + a2.w;
        float4 m1 = make_float4(OMA*s0, OMA*s1v, OMA*s2v, OMA*s3);
        float4 m2 = make_float4(
            ALPHA*OMA*s0 + OMA*OMA*(c1[i][0]+c2[i][0]),
            ALPHA*OMA*s1v + OMA*OMA*(c1[i][1]+c2[i][1]),
            ALPHA*OMA*s2v + OMA*OMA*(c1[i][2]+c2[i][2]),
            ALPHA*OMA*s3 + OMA*OMA*(c1[i][3]+c2[i][3]));
        *(float4*)&g_M1[row*Ndim + col] = m1;
        *(float4*)&g_M2[row*Ndim + col] = m2;
    }
}

// ============================================================
// K3: y1 = M1 @ x, y2 = M2 @ x  (dual output, shares x tile)
// ============================================================
__global__ void k_y(const float* __restrict__ x) {
    int bc = blockIdx.z;
    __shared__ float As1[32][36], As2[32][36], Bs[32][36];
    int tid = threadIdx.x;
    int tx = tid & 7, ty = tid >> 3;
    int bi = blockIdx.y, bj = blockIdx.x;
    const float* xb = x + (size_t)bc*NL;
    float acc1[4][4] = {}, acc2[4][4] = {};
    for (int kt = 0; kt < 5; kt++) {
        #pragma unroll
        for (int it = 0; it < 4; it++) {
            int g = tid + it*64;
            int m = g >> 3, k4 = g & 7;
            float4 v1 = *(const float4*)&g_M1[(bi*32+m)*Ndim + kt*32 + k4*4];
            float4 v2 = *(const float4*)&g_M2[(bi*32+m)*Ndim + kt*32 + k4*4];
            As1[k4*4+0][m] = v1.x; As1[k4*4+1][m] = v1.y;
            As1[k4*4+2][m] = v1.z; As1[k4*4+3][m] = v1.w;
            As2[k4*4+0][m] = v2.x; As2[k4*4+1][m] = v2.y;
            As2[k4*4+2][m] = v2.z; As2[k4*4+3][m] = v2.w;
            *(float4*)&Bs[m][k4*4] = *(const float4*)&xb[(kt*32+m)*Ldim + bj*32 + k4*4];
        }
        __syncthreads();
        #pragma unroll
        for (int k = 0; k < 32; k++) {
            float4 a1 = *(const float4*)&As1[k][ty*4];
            float4 a2 = *(const float4*)&As2[k][ty*4];
            float4 bv = *(const float4*)&Bs[k][tx*4];
            float aa1[4] = {a1.x,a1.y,a1.z,a1.w}, aa2[4] = {a2.x,a2.y,a2.z,a2.w};
            float bb[4] = {bv.x,bv.y,bv.z,bv.w};
            #pragma unroll
            for (int i = 0; i < 4; i++)
            #pragma unroll
            for (int j = 0; j < 4; j++) {
                acc1[i][j] += aa1[i]*bb[j];
                acc2[i][j] += aa2[i]*bb[j];
            }
        }
        __syncthreads();
    }
    #pragma unroll
    for (int i = 0; i < 4; i++) {
        size_t off = (size_t)bc*NL + (bi*32 + ty*4 + i)*Ldim + bj*32 + tx*4;
        *(float4*)&g_y1[off] = make_float4(acc1[i][0],acc1[i][1],acc1[i][2],acc1[i][3]);
        *(float4*)&g_y2[off] = make_float4(acc2[i][0],acc2[i][1],acc2[i][2],acc2[i][3]);
    }
}

// ============================================================
// K4: channel mix. 64 out ch x 96 in-K, per batch, 128 points/block.
//   K rows: [x(32, w'=2W0+2a(W1+W2)); y1(32, W1); y2(32, W2)]. Bias 2b.
// ============================================================
__global__ void __launch_bounds__(256) k_mix(
        const float* __restrict__ x,
        const float* __restrict__ We, const float* __restrict__ be,
        const float* __restrict__ Wp, const float* __restrict__ bp) {
    __shared__ float Ws[48][68];
    __shared__ float Hs[48][128];
    int b  = blockIdx.y;
    int p0 = blockIdx.x * 128;
    int tid = threadIdx.x;
    int o4 = tid & 15, pg = tid >> 4;
    float acc[4][8] = {};
    for (int kc = 0; kc < 2; kc++) {
        // weights chunk: 48 x 64
        for (int e = tid; e < 48*64; e += 256) {
            int kl = e >> 6, o = e & 63;
            int kg = kc*48 + kl;
            const float* W = (o < 32) ? We : Wp;
            int oo = o & 31;
            float w;
            if (kg < 32)
                w = 2.f*W[oo*96 + kg] + 2.f*ALPHA*(W[oo*96 + 32 + kg] + W[oo*96 + 64 + kg]);
            else
                w = W[oo*96 + kg];
            Ws[kl][o] = w;
        }
        // H chunk: 48 x 128 (float4 granularity)
        for (int e = tid; e < 48*32; e += 256) {
            int kl = e >> 5, c4 = e & 31;
            int kg = kc*48 + kl;
            const float* src = (kg < 32) ? x : ((kg < 64) ? g_y1 : g_y2);
            int cc = kg & 31;
            *(float4*)&Hs[kl][c4*4] =
                *(const float4*)&src[(size_t)(b*32 + cc)*NL + p0 + c4*4];
        }
        __syncthreads();
        #pragma unroll
        for (int k = 0; k < 48; k++) {
            float4 wv = *(const float4*)&Ws[k][o4*4];
            float4 h0 = *(const float4*)&Hs[k][pg*8];
            float4 h1 = *(const float4*)&Hs[k][pg*8 + 4];
            float wa[4] = {wv.x,wv.y,wv.z,wv.w};
            float hb[8] = {h0.x,h0.y,h0.z,h0.w,h1.x,h1.y,h1.z,h1.w};
            #pragma unroll
            for (int i = 0; i < 4; i++)
            #pragma unroll
            for (int j = 0; j < 8; j++)
                acc[i][j] += wa[i]*hb[j];
        }
        __syncthreads();
    }
    #pragma unroll
    for (int i = 0; i < 4; i++) {
        int o = o4*4 + i;
        float bias = 2.f * ((o < 32) ? be[o] : bp[o-32]);
        float* dst = (o < 32) ? g_embed : g_pool;
        int oo = o & 31;
        size_t off = (size_t)(b*32 + oo)*NL + p0 + pg*8;
        *(float4*)&dst[off]   = make_float4(acc[i][0]+bias, acc[i][1]+bias,
                                            acc[i][2]+bias, acc[i][3]+bias);
        *(float4*)&dst[off+4] = make_float4(acc[i][4]+bias, acc[i][5]+bias,
                                            acc[i][6]+bias, acc[i][7]+bias);
    }
}

// ============================================================
// K5: in-place softmax of g_pool over node axis
// ============================================================
__global__ void k_softmax() {
    int bc = blockIdx.x;
    int l = threadIdx.x;
    float* p = g_pool + (size_t)bc*NL;
    float m = -3.4e38f, d = 0.f;
    for (int n = 0; n < Ndim; n++) {
        float v = p[n*Ldim + l];
        float m2 = fmaxf(m, v);
        d = d * __expf(m - m2) + __expf(v - m2);
        m = m2;
    }
    float inv = 1.f / d;
    for (int n = 0; n < Ndim; n++)
        p[n*Ldim + l] = __expf(p[n*Ldim + l] - m) * inv;
}

// ============================================================
// Batched 160x160x160 GEMM, 32x32 tile, 4x4 micro, 64 threads.
// TA=true: C = A^T B (A stored [K,M], direct load); else C = A B (transpose load).
// ============================================================
template<bool TA>
__global__ void k_bgemm(const float* __restrict__ A, long sA,
                        const float* __restrict__ Bm, long sB,
                        float* __restrict__ Cm, long sC) {
    int bc = blockIdx.z;
    const float* Ab = A  + (size_t)bc*sA;
    const float* Bb = Bm + (size_t)bc*sB;
    float*       Cb = Cm + (size_t)bc*sC;
    __shared__ float As[32][36], Bs[32][36];
    int tid = threadIdx.x;
    int tx = tid & 7, ty = tid >> 3;
    int bi = blockIdx.y, bj = blockIdx.x;
    float acc[4][4] = {};
    for (int kt = 0; kt < 5; kt++) {
        #pragma unroll
        for (int it = 0; it < 4; it++) {
            int g = tid + it*64;
            if (TA) {
                int r = g >> 3, c4 = g & 7;
                *(float4*)&As[r][c4*4] =
                    *(const float4*)&Ab[(kt*32+r)*Ndim + bi*32 + c4*4];
            } else {
                int m = g >> 3, k4 = g & 7;
                float4 v = *(const float4*)&Ab[(bi*32+m)*Ndim + kt*32 + k4*4];
                As[k4*4+0][m] = v.x; As[k4*4+1][m] = v.y;
                As[k4*4+2][m] = v.z; As[k4*4+3][m] = v.w;
            }
            int r = g >> 3, c4 = g & 7;
            *(float4*)&Bs[r][c4*4] =
                *(const float4*)&Bb[(kt*32+r)*Ndim + bj*32 + c4*4];
        }
        __syncthreads();
        #pragma unroll
        for (int k = 0; k < 32; k++) {
            float4 av = *(const float4*)&As[k][ty*4];
            float4 bv = *(const float4*)&Bs[k][tx*4];
            float aa[4] = {av.x,av.y,av.z,av.w};
            float bb[4] = {bv.x,bv.y,bv.z,bv.w};
            #pragma unroll
            for (int i = 0; i < 4; i++)
            #pragma unroll
            for (int j = 0; j < 4; j++)
                acc[i][j] += aa[i]*bb[j];
        }
        __syncthreads();
    }
    #pragma unroll
    for (int i = 0; i < 4; i++)
        *(float4*)&Cb[(bi*32 + ty*4 + i)*Ldim + bj*32 + tx*4] =
            make_float4(acc[i][0], acc[i][1], acc[i][2], acc[i][3]);
}

// ============================================================
extern "C" void kernel_launch(void* const* d_in, const int* in_sizes, int n_in,
                              void* d_out, int out_size) {
    const float* x  = (const float*)d_in[0];
    const float* a  = (const float*)d_in[1];
    const float* We = (const float*)d_in[2];
    const float* be = (const float*)d_in[3];
    const float* Wp = (const float*)d_in[4];
    const float* bp = (const float*)d_in[5];
    float* out  = (float*)d_out;
    float* xnew = out;
    float* anew = out + (size_t)BC*NL;

    void *p_pool, *p_embed, *p_t;
    cudaGetSymbolAddress(&p_pool,  g_pool);
    cudaGetSymbolAddress(&p_embed, g_embed);
    cudaGetSymbolAddress(&p_t,     g_t);

    dim3 g55(5, 5, BC);

    k_norm_adj<<<Ndim, Ndim>>>(a);
    k_prep<<<dim3(5, 5), 64>>>();
    k_y<<<g55, 64>>>(x);
    k_mix<<<dim3(NL/128, Bdim), 256>>>(x, We, be, Wp, bp);
    k_softmax<<<BC, Ldim>>>();
    // x_new = s^T @ embed
    k_bgemm<true ><<<g55, 64>>>((const float*)p_pool, NL, (const float*)p_embed, NL, xnew, NL);
    // t = s @ a  (a shared across batches)
    k_bgemm<false><<<g55, 64>>>((const float*)p_pool, NL, a, 0, (float*)p_t, NL);
    // a_new = t @ s
    k_bgemm<false><<<g55, 64>>>((const float*)p_t, NL, (const float*)p_pool, NL, anew, NL);
}

// round 3
// speedup vs baseline: 2.6740x; 1.1645x over previous
#include <cuda_runtime.h>
#include <cstdint>

#define Bdim 32
#define Ndim 160
#define NL 25600           // 160*160
#define BC 1024            // 32*32
#define ALPHA 0.05f
#define OMA 0.95f

// ---- scratch (__device__ globals; no allocations) ----
__device__ float g_A1[Ndim*Ndim];
__device__ float g_A2[Ndim*Ndim];
__device__ float g_Ms[2*Ndim*Ndim];        // stacked [320][160]: rows 0-159 = M1, 160-319 = M2
__device__ float g_Wc[64*96];              // folded weights, [o][k] row-major
__device__ float g_y[(size_t)BC*2*NL];     // per bc: [320][160] = y1 rows 0-159, y2 rows 160-319
__device__ float g_embed[(size_t)BC*NL];
__device__ float g_pool [(size_t)BC*NL];   // becomes s after softmax
__device__ float g_t    [(size_t)BC*NL];   // s @ a

// ---------- tf32 helpers ----------
__device__ __forceinline__ uint32_t f2tf(float v) {
    uint32_t r; asm("cvt.rna.tf32.f32 %0, %1;" : "=r"(r) : "f"(v)); return r;
}
__device__ __forceinline__ float tfhi(float v) { return __uint_as_float(f2tf(v)); }
__device__ __forceinline__ float tflo(float v, float h) { return __uint_as_float(f2tf(v - h)); }

__device__ __forceinline__ void mma8(float* c, const uint32_t* a, const uint32_t* b) {
    asm volatile(
        "mma.sync.aligned.m16n8k8.row.col.f32.tf32.tf32.f32 "
        "{%0,%1,%2,%3}, {%4,%5,%6,%7}, {%8,%9}, {%0,%1,%2,%3};"
        : "+f"(c[0]), "+f"(c[1]), "+f"(c[2]), "+f"(c[3])
        : "r"(a[0]), "r"(a[1]), "r"(a[2]), "r"(a[3]), "r"(b[0]), "r"(b[1]));
}

// ============================================================
// K1: row-normalized (a+I) and (a^T+I)
// ============================================================
__global__ void k_norm_adj(const float* __restrict__ a) {
    int v = blockIdx.x;
    int t = threadIdx.x;
    __shared__ float s1[Ndim], s2[Ndim];
    __shared__ float r1, r2;
    float av = a[v*Ndim + t];
    float aw = a[t*Ndim + v];
    s1[t] = av; s2[t] = aw;
    __syncthreads();
    if (t == 0) {
        float x1 = 0.f, x2 = 0.f;
        for (int i = 0; i < Ndim; i++) { x1 += s1[i]; x2 += s2[i]; }
        r1 = x1 + 1.f; r2 = x2 + 1.f;
    }
    __syncthreads();
    float diag = (t == v) ? 1.f : 0.f;
    g_A1[v*Ndim + t] = (av + diag) / r1;
    g_A2[v*Ndim + t] = (aw + diag) / r2;
}

// ============================================================
// K2: Mstack: rows v    = M1 = (1-a)(A1+A2)
//             rows 160+v= M2 = a(1-a)(A1+A2) + (1-a)^2 (A1^2 + A2^2)
// (fp32 dual GEMM, tiny: 160^3*2)
// ============================================================
__global__ void k_prep() {
    __shared__ float As1[32][36], As2[32][36], Bs1[32][36], Bs2[32][36];
    int tid = threadIdx.x;
    int tx = tid & 7, ty = tid >> 3;
    int bi = blockIdx.y, bj = blockIdx.x;
    float c1[4][4] = {}, c2[4][4] = {};
    for (int kt = 0; kt < 5; kt++) {
        #pragma unroll
        for (int it = 0; it < 4; it++) {
            int g = tid + it*64;
            int m = g >> 3, k4 = g & 7;
            float4 v1 = *(const float4*)&g_A1[(bi*32+m)*Ndim + kt*32 + k4*4];
            float4 v2 = *(const float4*)&g_A2[(bi*32+m)*Ndim + kt*32 + k4*4];
            As1[k4*4+0][m] = v1.x; As1[k4*4+1][m] = v1.y;
            As1[k4*4+2][m] = v1.z; As1[k4*4+3][m] = v1.w;
            As2[k4*4+0][m] = v2.x; As2[k4*4+1][m] = v2.y;
            As2[k4*4+2][m] = v2.z; As2[k4*4+3][m] = v2.w;
            int r = g >> 3, c4 = g & 7;
            *(float4*)&Bs1[r][c4*4] = *(const float4*)&g_A1[(kt*32+r)*Ndim + bj*32 + c4*4];
            *(float4*)&Bs2[r][c4*4] = *(const float4*)&g_A2[(kt*32+r)*Ndim + bj*32 + c4*4];
        }
        __syncthreads();
        #pragma unroll
        for (int k = 0; k < 32; k++) {
            float4 a1 = *(const float4*)&As1[k][ty*4];
            float4 a2 = *(const float4*)&As2[k][ty*4];
            float4 b1 = *(const float4*)&Bs1[k][tx*4];
            float4 b2 = *(const float4*)&Bs2[k][tx*4];
            float aa1[4] = {a1.x,a1.y,a1.z,a1.w}, aa2[4] = {a2.x,a2.y,a2.z,a2.w};
            float bb1[4] = {b1.x,b1.y,b1.z,b1.w}, bb2[4] = {b2.x,b2.y,b2.z,b2.w};
            #pragma unroll
            for (int i = 0; i < 4; i++)
            #pragma unroll
            for (int j = 0; j < 4; j++) {
                c1[i][j] += aa1[i]*bb1[j];
                c2[i][j] += aa2[i]*bb2[j];
            }
        }
        __syncthreads();
    }
    #pragma unroll
    for (int i = 0; i < 4; i++) {
        int row = bi*32 + ty*4 + i;
        int col = bj*32 + tx*4;
        float4 a1 = *(const float4*)&g_A1[row*Ndim + col];
        float4 a2 = *(const float4*)&g_A2[row*Ndim + col];
        float s0 = a1.x + a2.x, s1v = a1.y + a2.y, s2v = a1.z + a2.z, s3 = a1.w + a2.w;
        *(float4*)&g_Ms[row*Ndim + col] = make_float4(OMA*s0, OMA*s1v, OMA*s2v, OMA*s3);
        *(float4*)&g_Ms[(160+row)*Ndim + col] = make_float4(
            ALPHA*OMA*s0  + OMA*OMA*(c1[i][0]+c2[i][0]),
            ALPHA*OMA*s1v + OMA*OMA*(c1[i][1]+c2[i][1]),
            ALPHA*OMA*s2v + OMA*OMA*(c1[i][2]+c2[i][2]),
            ALPHA*OMA*s3  + OMA*OMA*(c1[i][3]+c2[i][3]));
    }
}

// ============================================================
// K3: folded weights Wc[o][k], o<32 -> We (embed), o>=32 -> Wp (pool)
//   k<32: 2W[.,k] + 2a(W[.,k+32] + W[.,k+64]) ; else W[.,k]
// ============================================================
__global__ void k_wcprep(const float* __restrict__ We, const float* __restrict__ Wp) {
    int idx = blockIdx.x*256 + threadIdx.x;
    if (idx >= 64*96) return;
    int o = idx / 96, k = idx % 96;
    const float* W = (o < 32) ? We : Wp;
    int oo = o & 31;
    float v;
    if (k < 32) v = 2.f*W[oo*96 + k] + 2.f*ALPHA*(W[oo*96 + k + 32] + W[oo*96 + k + 64]);
    else        v = W[oo*96 + k];
    g_Wc[o*96 + k] = v;
}

// ============================================================
// Generic batched TF32 split-precision GEMM.
// C[M,N] = A·B per batch. 64x64 block tile, 4 warps (2x2), BK=32.
// TA=false: A stored [M][K] (row-major, lda); TA=true: A stored [K][M].
// B stored [K][N] (ldb). All of M,N,K %4==0; K%32==0.
// ============================================================
template<bool TA>
__global__ void __launch_bounds__(128) k_tgemm(
    const float* __restrict__ A, long sA, int lda,
    const float* __restrict__ B, long sB, int ldb,
    float* __restrict__ C, long sC, int ldc,
    int M, int N, int K)
{
    __shared__ float Ash[64*36], Asl[64*36];   // [m][k] pad 36
    __shared__ float Bsh[32*68], Bsl[32*68];   // [k][n] pad 68
    int bc = blockIdx.z;
    const float* Ab = A + (size_t)bc*sA;
    const float* Bb = B + (size_t)bc*sB;
    float*       Cb = C + (size_t)bc*sC;
    int m0 = blockIdx.y*64, n0 = blockIdx.x*64;
    int tid = threadIdx.x, lane = tid & 31, wid = tid >> 5;
    int wm = (wid & 1)*32, wn = (wid >> 1)*32;
    int g = lane >> 2, t = lane & 3;
    float acc[2][4][4] = {};

    for (int kt = 0; kt < K; kt += 32) {
        // ---- stage A ----
        if (TA) {
            #pragma unroll
            for (int i = 0; i < 4; i++) {
                int s = tid + i*128;
                int k = s >> 4, m4 = (s & 15)*4;
                float4 v = make_float4(0,0,0,0);
                if (m0 + m4 < M) v = *(const float4*)&Ab[(size_t)(kt+k)*lda + m0 + m4];
                float h0=tfhi(v.x),h1=tfhi(v.y),h2=tfhi(v.z),h3=tfhi(v.w);
                Ash[(m4+0)*36 + k] = h0; Asl[(m4+0)*36 + k] = tflo(v.x,h0);
                Ash[(m4+1)*36 + k] = h1; Asl[(m4+1)*36 + k] = tflo(v.y,h1);
                Ash[(m4+2)*36 + k] = h2; Asl[(m4+2)*36 + k] = tflo(v.z,h2);
                Ash[(m4+3)*36 + k] = h3; Asl[(m4+3)*36 + k] = tflo(v.w,h3);
            }
        } else {
            #pragma unroll
            for (int i = 0; i < 4; i++) {
                int s = tid + i*128;
                int m = s >> 3, k4 = (s & 7)*4;
                float4 v = make_float4(0,0,0,0);
                if (m0 + m < M) v = *(const float4*)&Ab[(size_t)(m0+m)*lda + kt + k4];
                float h0=tfhi(v.x),h1=tfhi(v.y),h2=tfhi(v.z),h3=tfhi(v.w);
                *(float4*)&Ash[m*36 + k4] = make_float4(h0,h1,h2,h3);
                *(float4*)&Asl[m*36 + k4] = make_float4(tflo(v.x,h0),tflo(v.y,h1),
                                                        tflo(v.z,h2),tflo(v.w,h3));
            }
        }
        // ---- stage B ----
        #pragma unroll
        for (int i = 0; i < 4; i++) {
            int s = tid + i*128;
            int k = s >> 4, n4 = (s & 15)*4;
            float4 v = make_float4(0,0,0,0);
            if (n0 + n4 < N) v = *(const float4*)&Bb[(size_t)(kt+k)*ldb + n0 + n4];
            float h0=tfhi(v.x),h1=tfhi(v.y),h2=tfhi(v.z),h3=tfhi(v.w);
            *(float4*)&Bsh[k*68 + n4] = make_float4(h0,h1,h2,h3);
            *(float4*)&Bsl[k*68 + n4] = make_float4(tflo(v.x,h0),tflo(v.y,h1),
                                                    tflo(v.z,h2),tflo(v.w,h3));
        }
        __syncthreads();
        // ---- compute 4 k8-steps ----
        #pragma unroll
        for (int kk = 0; kk < 32; kk += 8) {
            uint32_t Af[2][4], Al_[2][4], Bf[4][2], Bl_[4][2];
            #pragma unroll
            for (int mt = 0; mt < 2; mt++) {
                int mr = wm + mt*16 + g;
                Af[mt][0]  = __float_as_uint(Ash[(mr  )*36 + kk + t]);
                Af[mt][1]  = __float_as_uint(Ash[(mr+8)*36 + kk + t]);
                Af[mt][2]  = __float_as_uint(Ash[(mr  )*36 + kk + t + 4]);
                Af[mt][3]  = __float_as_uint(Ash[(mr+8)*36 + kk + t + 4]);
                Al_[mt][0] = __float_as_uint(Asl[(mr  )*36 + kk + t]);
                Al_[mt][1] = __float_as_uint(Asl[(mr+8)*36 + kk + t]);
                Al_[mt][2] = __float_as_uint(Asl[(mr  )*36 + kk + t + 4]);
                Al_[mt][3] = __float_as_uint(Asl[(mr+8)*36 + kk + t + 4]);
            }
            #pragma unroll
            for (int nt = 0; nt < 4; nt++) {
                int nc = wn + nt*8 + g;
                Bf[nt][0]  = __float_as_uint(Bsh[(kk+t  )*68 + nc]);
                Bf[nt][1]  = __float_as_uint(Bsh[(kk+t+4)*68 + nc]);
                Bl_[nt][0] = __float_as_uint(Bsl[(kk+t  )*68 + nc]);
                Bl_[nt][1] = __float_as_uint(Bsl[(kk+t+4)*68 + nc]);
            }
            #pragma unroll
            for (int mt = 0; mt < 2; mt++)
            #pragma unroll
            for (int nt = 0; nt < 4; nt++) {
                mma8(acc[mt][nt], Af[mt],  Bf[nt]);
                mma8(acc[mt][nt], Af[mt],  Bl_[nt]);
                mma8(acc[mt][nt], Al_[mt], Bf[nt]);
            }
        }
        __syncthreads();
    }
    // ---- epilogue ----
    #pragma unroll
    for (int mt = 0; mt < 2; mt++) {
        int r0 = m0 + wm + mt*16 + g;
        #pragma unroll
        for (int nt = 0; nt < 4; nt++) {
            int c0 = n0 + wn + nt*8 + 2*t;
            if (c0 < N) {
                if (r0 < M)
                    *(float2*)&Cb[(size_t)r0*ldc + c0] =
                        make_float2(acc[mt][nt][0], acc[mt][nt][1]);
                if (r0 + 8 < M)
                    *(float2*)&Cb[(size_t)(r0+8)*ldc + c0] =
                        make_float2(acc[mt][nt][2], acc[mt][nt][3]);
            }
        }
    }
}

// ============================================================
// K5: channel mix as TF32 GEMM. M=64 (out ch), K=96, N=64-point tiles.
//   A = g_Wc [64][96]; B rows: k<32 -> x, k<64 -> y1, else y2.
//   Epilogue: +2*bias, rows 0-31 -> g_embed, rows 32-63 -> g_pool.
// ============================================================
__global__ void __launch_bounds__(128) k_mix_t(
    const float* __restrict__ x,
    const float* __restrict__ be, const float* __restrict__ bp)
{
    __shared__ float Ash[64*36], Asl[64*36];
    __shared__ float Bsh[32*68], Bsl[32*68];
    int b = blockIdx.y;
    int p0 = blockIdx.x*64;
    int tid = threadIdx.x, lane = tid & 31, wid = tid >> 5;
    int wm = (wid & 1)*32, wn = (wid >> 1)*32;
    int g = lane >> 2, t = lane & 3;
    float acc[2][4][4] = {};

    for (int kt = 0; kt < 96; kt += 32) {
        #pragma unroll
        for (int i = 0; i < 4; i++) {
            int s = tid + i*128;
            int m = s >> 3, k4 = (s & 7)*4;
            float4 v = *(const float4*)&g_Wc[m*96 + kt + k4];
            float h0=tfhi(v.x),h1=tfhi(v.y),h2=tfhi(v.z),h3=tfhi(v.w);
            *(float4*)&Ash[m*36 + k4] = make_float4(h0,h1,h2,h3);
            *(float4*)&Asl[m*36 + k4] = make_float4(tflo(v.x,h0),tflo(v.y,h1),
                                                    tflo(v.z,h2),tflo(v.w,h3));
        }
        #pragma unroll
        for (int i = 0; i < 4; i++) {
            int s = tid + i*128;
            int k = s >> 4, n4 = (s & 15)*4;
            int kg = kt + k;
            int c = kg & 31;
            const float* src;
            if (kg < 32)      src = x    + ((size_t)b*32 + c)*NL;
            else if (kg < 64) src = g_y  + ((size_t)b*32 + c)*(2*NL);
            else              src = g_y  + ((size_t)b*32 + c)*(2*NL) + NL;
            float4 v = *(const float4*)&src[p0 + n4];
            float h0=tfhi(v.x),h1=tfhi(v.y),h2=tfhi(v.z),h3=tfhi(v.w);
            *(float4*)&Bsh[k*68 + n4] = make_float4(h0,h1,h2,h3);
            *(float4*)&Bsl[k*68 + n4] = make_float4(tflo(v.x,h0),tflo(v.y,h1),
                                                    tflo(v.z,h2),tflo(v.w,h3));
        }
        __syncthreads();
        #pragma unroll
        for (int kk = 0; kk < 32; kk += 8) {
            uint32_t Af[2][4], Al_[2][4], Bf[4][2], Bl_[4][2];
            #pragma unroll
            for (int mt = 0; mt < 2; mt++) {
                int mr = wm + mt*16 + g;
                Af[mt][0]  = __float_as_uint(Ash[(mr  )*36 + kk + t]);
                Af[mt][1]  = __float_as_uint(Ash[(mr+8)*36 + kk + t]);
                Af[mt][2]  = __float_as_uint(Ash[(mr  )*36 + kk + t + 4]);
                Af[mt][3]  = __float_as_uint(Ash[(mr+8)*36 + kk + t + 4]);
                Al_[mt][0] = __float_as_uint(Asl[(mr  )*36 + kk + t]);
                Al_[mt][1] = __float_as_uint(Asl[(mr+8)*36 + kk + t]);
                Al_[mt][2] = __float_as_uint(Asl[(mr  )*36 + kk + t + 4]);
                Al_[mt][3] = __float_as_uint(Asl[(mr+8)*36 + kk + t + 4]);
            }
            #pragma unroll
            for (int nt = 0; nt < 4; nt++) {
                int nc = wn + nt*8 + g;
                Bf[nt][0]  = __float_as_uint(Bsh[(kk+t  )*68 + nc]);
                Bf[nt][1]  = __float_as_uint(Bsh[(kk+t+4)*68 + nc]);
                Bl_[nt][0] = __float_as_uint(Bsl[(kk+t  )*68 + nc]);
                Bl_[nt][1] = __float_as_uint(Bsl[(kk+t+4)*68 + nc]);
            }
            #pragma unroll
            for (int mt = 0; mt < 2; mt++)
            #pragma unroll
            for (int nt = 0; nt < 4; nt++) {
                mma8(acc[mt][nt], Af[mt],  Bf[nt]);
                mma8(acc[mt][nt], Af[mt],  Bl_[nt]);
                mma8(acc[mt][nt], Al_[mt], Bf[nt]);
            }
        }
        __syncthreads();
    }
    #pragma unroll
    for (int mt = 0; mt < 2; mt++) {
        #pragma unroll
        for (int rr = 0; rr < 2; rr++) {
            int o = wm + mt*16 + g + rr*8;
            float bias = 2.f * ((o < 32) ? be[o] : bp[o-32]);
            float* dst = (o < 32) ? g_embed : g_pool;
            size_t base = ((size_t)b*32 + (o & 31))*NL + p0;
            #pragma unroll
            for (int nt = 0; nt < 4; nt++) {
                int c0 = wn + nt*8 + 2*t;
                *(float2*)&dst[base + c0] =
                    make_float2(acc[mt][nt][rr*2+0] + bias, acc[mt][nt][rr*2+1] + bias);
            }
        }
    }
}

// ============================================================
// K6: in-place softmax of g_pool over node axis
// ============================================================
__global__ void k_softmax() {
    int bc = blockIdx.x;
    int l = threadIdx.x;
    float* p = g_pool + (size_t)bc*NL;
    float m = -3.4e38f, d = 0.f;
    for (int n = 0; n < Ndim; n++) {
        float v = p[n*Ndim + l];
        float m2 = fmaxf(m, v);
        d = d * __expf(m - m2) + __expf(v - m2);
        m = m2;
    }
    float inv = 1.f / d;
    for (int n = 0; n < Ndim; n++)
        p[n*Ndim + l] = __expf(p[n*Ndim + l] - m) * inv;
}

// ============================================================
extern "C" void kernel_launch(void* const* d_in, const int* in_sizes, int n_in,
                              void* d_out, int out_size) {
    const float* x  = (const float*)d_in[0];
    const float* a  = (const float*)d_in[1];
    const float* We = (const float*)d_in[2];
    const float* be = (const float*)d_in[3];
    const float* Wp = (const float*)d_in[4];
    const float* bp = (const float*)d_in[5];
    float* out  = (float*)d_out;
    float* xnew = out;
    float* anew = out + (size_t)BC*NL;

    void *p_pool, *p_embed, *p_t, *p_Ms, *p_y;
    cudaGetSymbolAddress(&p_pool,  g_pool);
    cudaGetSymbolAddress(&p_embed, g_embed);
    cudaGetSymbolAddress(&p_t,     g_t);
    cudaGetSymbolAddress(&p_Ms,    g_Ms);
    cudaGetSymbolAddress(&p_y,     g_y);

    k_norm_adj<<<Ndim, Ndim>>>(a);
    k_prep<<<dim3(5, 5), 64>>>();
    k_wcprep<<<(64*96 + 255)/256, 256>>>(We, Wp);

    // ystack = Mstack @ x : M=320, N=160, K=160 per batch (A shared)
    k_tgemm<false><<<dim3(3, 5, BC), 128>>>(
        (const float*)p_Ms, 0, Ndim, x, NL, Ndim,
        (float*)p_y, 2*NL, Ndim, 320, Ndim, Ndim);

    // channel mix -> embed, pool
    k_mix_t<<<dim3(NL/64, Bdim), 128>>>(x, be, bp);

    k_softmax<<<BC, Ndim>>>();

    // x_new = s^T @ embed : A = s stored [K=n][M=l] -> TA
    k_tgemm<true><<<dim3(3, 3, BC), 128>>>(
        (const float*)p_pool, NL, Ndim, (const float*)p_embed, NL, Ndim,
        xnew, NL, Ndim, Ndim, Ndim, Ndim);

    // t = s @ a  (B shared)
    k_tgemm<false><<<dim3(3, 3, BC), 128>>>(
        (const float*)p_pool, NL, Ndim, a, 0, Ndim,
        (float*)p_t, NL, Ndim, Ndim, Ndim, Ndim);

    // a_new = t @ s
    k_tgemm<false><<<dim3(3, 3, BC), 128>>>(
        (const float*)p_t, NL, Ndim, (const float*)p_pool, NL, Ndim,
        anew, NL, Ndim, Ndim, Ndim, Ndim);
}

// round 4
// speedup vs baseline: 3.2031x; 1.1979x over previous
#include <cuda_runtime.h>
#include <cstdint>

#define Bdim 32
#define Ndim 160
#define NL 25600           // 160*160
#define BC 1024            // 32*32
#define ALPHA 0.05f
#define OMA 0.95f

// ---- scratch (__device__ globals; no allocations) ----
__device__ float g_A1[Ndim*Ndim];
__device__ float g_A2[Ndim*Ndim];
__device__ float g_Ms[2*Ndim*Ndim];        // stacked [320][160]: rows 0-159 = M1, 160-319 = M2
__device__ float g_Wc[64*96];              // folded weights, [o][k] row-major
__device__ float g_y[(size_t)BC*2*NL];     // per bc: [320][160] = y1 rows 0-159, y2 rows 160-319
__device__ float g_embed[(size_t)BC*NL];
__device__ float g_pool [(size_t)BC*NL];   // becomes s after softmax
__device__ float g_t    [(size_t)BC*NL];   // s @ a

// ---------- tf32 helpers ----------
__device__ __forceinline__ uint32_t f2tf(float v) {
    uint32_t r; asm("cvt.rna.tf32.f32 %0, %1;" : "=r"(r) : "f"(v)); return r;
}
__device__ __forceinline__ float tfhi(float v) { return __uint_as_float(f2tf(v)); }
__device__ __forceinline__ float tflo(float v, float h) { return __uint_as_float(f2tf(v - h)); }

__device__ __forceinline__ void mma8(float* c, const uint32_t* a, const uint32_t* b) {
    asm volatile(
        "mma.sync.aligned.m16n8k8.row.col.f32.tf32.tf32.f32 "
        "{%0,%1,%2,%3}, {%4,%5,%6,%7}, {%8,%9}, {%0,%1,%2,%3};"
        : "+f"(c[0]), "+f"(c[1]), "+f"(c[2]), "+f"(c[3])
        : "r"(a[0]), "r"(a[1]), "r"(a[2]), "r"(a[3]), "r"(b[0]), "r"(b[1]));
}

// ============================================================
// K1: row-normalized (a+I) and (a^T+I)
// ============================================================
__global__ void k_norm_adj(const float* __restrict__ a) {
    int v = blockIdx.x;
    int t = threadIdx.x;
    __shared__ float s1[Ndim], s2[Ndim];
    __shared__ float r1, r2;
    float av = a[v*Ndim + t];
    float aw = a[t*Ndim + v];
    s1[t] = av; s2[t] = aw;
    __syncthreads();
    if (t == 0) {
        float x1 = 0.f, x2 = 0.f;
        for (int i = 0; i < Ndim; i++) { x1 += s1[i]; x2 += s2[i]; }
        r1 = x1 + 1.f; r2 = x2 + 1.f;
    }
    __syncthreads();
    float diag = (t == v) ? 1.f : 0.f;
    g_A1[v*Ndim + t] = (av + diag) / r1;
    g_A2[v*Ndim + t] = (aw + diag) / r2;
}

// ============================================================
// K2: Mstack: rows v     = M1 = (1-a)(A1+A2)
//             rows 160+v = M2 = a(1-a)(A1+A2) + (1-a)^2 (A1^2 + A2^2)
// ============================================================
__global__ void k_prep() {
    __shared__ float As1[32][36], As2[32][36], Bs1[32][36], Bs2[32][36];
    int tid = threadIdx.x;
    int tx = tid & 7, ty = tid >> 3;
    int bi = blockIdx.y, bj = blockIdx.x;
    float c1[4][4] = {}, c2[4][4] = {};
    for (int kt = 0; kt < 5; kt++) {
        #pragma unroll
        for (int it = 0; it < 4; it++) {
            int g = tid + it*64;
            int m = g >> 3, k4 = g & 7;
            float4 v1 = *(const float4*)&g_A1[(bi*32+m)*Ndim + kt*32 + k4*4];
            float4 v2 = *(const float4*)&g_A2[(bi*32+m)*Ndim + kt*32 + k4*4];
            As1[k4*4+0][m] = v1.x; As1[k4*4+1][m] = v1.y;
            As1[k4*4+2][m] = v1.z; As1[k4*4+3][m] = v1.w;
            As2[k4*4+0][m] = v2.x; As2[k4*4+1][m] = v2.y;
            As2[k4*4+2][m] = v2.z; As2[k4*4+3][m] = v2.w;
            int r = g >> 3, c4 = g & 7;
            *(float4*)&Bs1[r][c4*4] = *(const float4*)&g_A1[(kt*32+r)*Ndim + bj*32 + c4*4];
            *(float4*)&Bs2[r][c4*4] = *(const float4*)&g_A2[(kt*32+r)*Ndim + bj*32 + c4*4];
        }
        __syncthreads();
        #pragma unroll
        for (int k = 0; k < 32; k++) {
            float4 a1 = *(const float4*)&As1[k][ty*4];
            float4 a2 = *(const float4*)&As2[k][ty*4];
            float4 b1 = *(const float4*)&Bs1[k][tx*4];
            float4 b2 = *(const float4*)&Bs2[k][tx*4];
            float aa1[4] = {a1.x,a1.y,a1.z,a1.w}, aa2[4] = {a2.x,a2.y,a2.z,a2.w};
            float bb1[4] = {b1.x,b1.y,b1.z,b1.w}, bb2[4] = {b2.x,b2.y,b2.z,b2.w};
            #pragma unroll
            for (int i = 0; i < 4; i++)
            #pragma unroll
            for (int j = 0; j < 4; j++) {
                c1[i][j] += aa1[i]*bb1[j];
                c2[i][j] += aa2[i]*bb2[j];
            }
        }
        __syncthreads();
    }
    #pragma unroll
    for (int i = 0; i < 4; i++) {
        int row = bi*32 + ty*4 + i;
        int col = bj*32 + tx*4;
        float4 a1 = *(const float4*)&g_A1[row*Ndim + col];
        float4 a2 = *(const float4*)&g_A2[row*Ndim + col];
        float s0 = a1.x + a2.x, s1v = a1.y + a2.y, s2v = a1.z + a2.z, s3 = a1.w + a2.w;
        *(float4*)&g_Ms[row*Ndim + col] = make_float4(OMA*s0, OMA*s1v, OMA*s2v, OMA*s3);
        *(float4*)&g_Ms[(160+row)*Ndim + col] = make_float4(
            ALPHA*OMA*s0  + OMA*OMA*(c1[i][0]+c2[i][0]),
            ALPHA*OMA*s1v + OMA*OMA*(c1[i][1]+c2[i][1]),
            ALPHA*OMA*s2v + OMA*OMA*(c1[i][2]+c2[i][2]),
            ALPHA*OMA*s3  + OMA*OMA*(c1[i][3]+c2[i][3]));
    }
}

// ============================================================
// K3: folded weights Wc[o][k]
// ============================================================
__global__ void k_wcprep(const float* __restrict__ We, const float* __restrict__ Wp) {
    int idx = blockIdx.x*256 + threadIdx.x;
    if (idx >= 64*96) return;
    int o = idx / 96, k = idx % 96;
    const float* W = (o < 32) ? We : Wp;
    int oo = o & 31;
    float v;
    if (k < 32) v = 2.f*W[oo*96 + k] + 2.f*ALPHA*(W[oo*96 + k + 32] + W[oo*96 + k + 64]);
    else        v = W[oo*96 + k];
    g_Wc[o*96 + k] = v;
}

// ============================================================
// K4: batched TF32 split GEMM, one CTA = full 160x160 output tile.
// 320 threads = 10 warps arranged 2(M) x 5(N); warp tile 80x32.
// K = 160 (5 chunks of 32). Exact fit, no guards.
// TA=false: A stored [M][K]; TA=true: A stored [K][M].
// m0 = blockIdx.y*160 row offset into A/C (for stacked-M GEMM).
// dyn smem: Ash/Asl [160][36], Bsh/Bsl [32][164]  (88064 B)
// ============================================================
#define SMEM_TG (22016*4)
template<bool TA>
__global__ void __launch_bounds__(320, 1) k_tgemm2(
    const float* __restrict__ A, long sA, int lda,
    const float* __restrict__ B, long sB, int ldb,
    float* __restrict__ C, long sC, int ldc)
{
    extern __shared__ float sm[];
    float* Ash = sm;               // 160*36
    float* Asl = sm + 5760;
    float* Bsh = sm + 11520;       // 32*164
    float* Bsl = sm + 16768;

    int bc = blockIdx.x;
    int m0 = blockIdx.y * 160;
    const float* Ab = A + (size_t)bc*sA;
    const float* Bb = B + (size_t)bc*sB;
    float*       Cb = C + (size_t)bc*sC;

    int tid = threadIdx.x, lane = tid & 31, wid = tid >> 5;
    int wmi = wid & 1, wni = wid >> 1;       // 2 x 5
    int g = lane >> 2, t = lane & 3;

    float acc[5][4][4] = {};

    for (int kt = 0; kt < 160; kt += 32) {
        // ---- stage A: [160][32] -> Ash/Asl [m][k] ----
        if (TA) {
            #pragma unroll
            for (int i = 0; i < 4; i++) {
                int s = tid + i*320;             // 0..1279
                int k = s / 40, m4 = (s % 40)*4;
                float4 v = *(const float4*)&Ab[(size_t)(kt+k)*lda + m0 + m4];
                float h0=tfhi(v.x),h1=tfhi(v.y),h2=tfhi(v.z),h3=tfhi(v.w);
                Ash[(m4+0)*36 + k] = h0; Asl[(m4+0)*36 + k] = tflo(v.x,h0);
                Ash[(m4+1)*36 + k] = h1; Asl[(m4+1)*36 + k] = tflo(v.y,h1);
                Ash[(m4+2)*36 + k] = h2; Asl[(m4+2)*36 + k] = tflo(v.z,h2);
                Ash[(m4+3)*36 + k] = h3; Asl[(m4+3)*36 + k] = tflo(v.w,h3);
            }
        } else {
            #pragma unroll
            for (int i = 0; i < 4; i++) {
                int s = tid + i*320;
                int m = s >> 3, k4 = (s & 7)*4;
                float4 v = *(const float4*)&Ab[(size_t)(m0+m)*lda + kt + k4];
                float h0=tfhi(v.x),h1=tfhi(v.y),h2=tfhi(v.z),h3=tfhi(v.w);
                *(float4*)&Ash[m*36 + k4] = make_float4(h0,h1,h2,h3);
                *(float4*)&Asl[m*36 + k4] = make_float4(tflo(v.x,h0),tflo(v.y,h1),
                                                        tflo(v.z,h2),tflo(v.w,h3));
            }
        }
        // ---- stage B: [32][160] -> Bsh/Bsl [k][n] ----
        #pragma unroll
        for (int i = 0; i < 4; i++) {
            int s = tid + i*320;
            int k = s / 40, n4 = (s % 40)*4;
            float4 v = *(const float4*)&Bb[(size_t)(kt+k)*ldb + n4];
            float h0=tfhi(v.x),h1=tfhi(v.y),h2=tfhi(v.z),h3=tfhi(v.w);
            *(float4*)&Bsh[k*164 + n4] = make_float4(h0,h1,h2,h3);
            *(float4*)&Bsl[k*164 + n4] = make_float4(tflo(v.x,h0),tflo(v.y,h1),
                                                     tflo(v.z,h2),tflo(v.w,h3));
        }
        __syncthreads();
        // ---- compute: 4 k8 steps ----
        #pragma unroll
        for (int kk = 0; kk < 32; kk += 8) {
            uint32_t Afh[5][4], Afl[5][4];
            #pragma unroll
            for (int mt = 0; mt < 5; mt++) {
                int mr = wmi*80 + mt*16 + g;
                Afh[mt][0] = __float_as_uint(Ash[(mr  )*36 + kk + t]);
                Afh[mt][1] = __float_as_uint(Ash[(mr+8)*36 + kk + t]);
                Afh[mt][2] = __float_as_uint(Ash[(mr  )*36 + kk + t + 4]);
                Afh[mt][3] = __float_as_uint(Ash[(mr+8)*36 + kk + t + 4]);
                Afl[mt][0] = __float_as_uint(Asl[(mr  )*36 + kk + t]);
                Afl[mt][1] = __float_as_uint(Asl[(mr+8)*36 + kk + t]);
                Afl[mt][2] = __float_as_uint(Asl[(mr  )*36 + kk + t + 4]);
                Afl[mt][3] = __float_as_uint(Asl[(mr+8)*36 + kk + t + 4]);
            }
            #pragma unroll
            for (int nt = 0; nt < 4; nt++) {
                int nc = wni*32 + nt*8 + g;
                uint32_t bh[2], bl[2];
                bh[0] = __float_as_uint(Bsh[(kk+t  )*164 + nc]);
                bh[1] = __float_as_uint(Bsh[(kk+t+4)*164 + nc]);
                bl[0] = __float_as_uint(Bsl[(kk+t  )*164 + nc]);
                bl[1] = __float_as_uint(Bsl[(kk+t+4)*164 + nc]);
                #pragma unroll
                for (int mt = 0; mt < 5; mt++) {
                    mma8(acc[mt][nt], Afh[mt], bh);
                    mma8(acc[mt][nt], Afh[mt], bl);
                    mma8(acc[mt][nt], Afl[mt], bh);
                }
            }
        }
        __syncthreads();
    }
    // ---- epilogue (exact fit, no guards) ----
    #pragma unroll
    for (int mt = 0; mt < 5; mt++) {
        int r0 = m0 + wmi*80 + mt*16 + g;
        #pragma unroll
        for (int nt = 0; nt < 4; nt++) {
            int c0 = wni*32 + nt*8 + 2*t;
            *(float2*)&Cb[(size_t)r0*ldc + c0] =
                make_float2(acc[mt][nt][0], acc[mt][nt][1]);
            *(float2*)&Cb[(size_t)(r0+8)*ldc + c0] =
                make_float2(acc[mt][nt][2], acc[mt][nt][3]);
        }
    }
}

// ============================================================
// K5: channel mix as TF32 GEMM (unchanged from R3).
// ============================================================
__global__ void __launch_bounds__(128) k_mix_t(
    const float* __restrict__ x,
    const float* __restrict__ be, const float* __restrict__ bp)
{
    __shared__ float Ash[64*36], Asl[64*36];
    __shared__ float Bsh[32*68], Bsl[32*68];
    int b = blockIdx.y;
    int p0 = blockIdx.x*64;
    int tid = threadIdx.x, lane = tid & 31, wid = tid >> 5;
    int wm = (wid & 1)*32, wn = (wid >> 1)*32;
    int g = lane >> 2, t = lane & 3;
    float acc[2][4][4] = {};

    for (int kt = 0; kt < 96; kt += 32) {
        #pragma unroll
        for (int i = 0; i < 4; i++) {
            int s = tid + i*128;
            int m = s >> 3, k4 = (s & 7)*4;
            float4 v = *(const float4*)&g_Wc[m*96 + kt + k4];
            float h0=tfhi(v.x),h1=tfhi(v.y),h2=tfhi(v.z),h3=tfhi(v.w);
            *(float4*)&Ash[m*36 + k4] = make_float4(h0,h1,h2,h3);
            *(float4*)&Asl[m*36 + k4] = make_float4(tflo(v.x,h0),tflo(v.y,h1),
                                                    tflo(v.z,h2),tflo(v.w,h3));
        }
        #pragma unroll
        for (int i = 0; i < 4; i++) {
            int s = tid + i*128;
            int k = s >> 4, n4 = (s & 15)*4;
            int kg = kt + k;
            int c = kg & 31;
            const float* src;
            if (kg < 32)      src = x    + ((size_t)b*32 + c)*NL;
            else if (kg < 64) src = g_y  + ((size_t)b*32 + c)*(2*NL);
            else              src = g_y  + ((size_t)b*32 + c)*(2*NL) + NL;
            float4 v = *(const float4*)&src[p0 + n4];
            float h0=tfhi(v.x),h1=tfhi(v.y),h2=tfhi(v.z),h3=tfhi(v.w);
            *(float4*)&Bsh[k*68 + n4] = make_float4(h0,h1,h2,h3);
            *(float4*)&Bsl[k*68 + n4] = make_float4(tflo(v.x,h0),tflo(v.y,h1),
                                                    tflo(v.z,h2),tflo(v.w,h3));
        }
        __syncthreads();
        #pragma unroll
        for (int kk = 0; kk < 32; kk += 8) {
            uint32_t Af[2][4], Al_[2][4], Bf[4][2], Bl_[4][2];
            #pragma unroll
            for (int mt = 0; mt < 2; mt++) {
                int mr = wm + mt*16 + g;
                Af[mt][0]  = __float_as_uint(Ash[(mr  )*36 + kk + t]);
                Af[mt][1]  = __float_as_uint(Ash[(mr+8)*36 + kk + t]);
                Af[mt][2]  = __float_as_uint(Ash[(mr  )*36 + kk + t + 4]);
                Af[mt][3]  = __float_as_uint(Ash[(mr+8)*36 + kk + t + 4]);
                Al_[mt][0] = __float_as_uint(Asl[(mr  )*36 + kk + t]);
                Al_[mt][1] = __float_as_uint(Asl[(mr+8)*36 + kk + t]);
                Al_[mt][2] = __float_as_uint(Asl[(mr  )*36 + kk + t + 4]);
                Al_[mt][3] = __float_as_uint(Asl[(mr+8)*36 + kk + t + 4]);
            }
            #pragma unroll
            for (int nt = 0; nt < 4; nt++) {
                int nc = wn + nt*8 + g;
                Bf[nt][0]  = __float_as_uint(Bsh[(kk+t  )*68 + nc]);
                Bf[nt][1]  = __float_as_uint(Bsh[(kk+t+4)*68 + nc]);
                Bl_[nt][0] = __float_as_uint(Bsl[(kk+t  )*68 + nc]);
                Bl_[nt][1] = __float_as_uint(Bsl[(kk+t+4)*68 + nc]);
            }
            #pragma unroll
            for (int mt = 0; mt < 2; mt++)
            #pragma unroll
            for (int nt = 0; nt < 4; nt++) {
                mma8(acc[mt][nt], Af[mt],  Bf[nt]);
                mma8(acc[mt][nt], Af[mt],  Bl_[nt]);
                mma8(acc[mt][nt], Al_[mt], Bf[nt]);
            }
        }
        __syncthreads();
    }
    #pragma unroll
    for (int mt = 0; mt < 2; mt++) {
        #pragma unroll
        for (int rr = 0; rr < 2; rr++) {
            int o = wm + mt*16 + g + rr*8;
            float bias = 2.f * ((o < 32) ? be[o] : bp[o-32]);
            float* dst = (o < 32) ? g_embed : g_pool;
            size_t base = ((size_t)b*32 + (o & 31))*NL + p0;
            #pragma unroll
            for (int nt = 0; nt < 4; nt++) {
                int c0 = wn + nt*8 + 2*t;
                *(float2*)&dst[base + c0] =
                    make_float2(acc[mt][nt][rr*2+0] + bias, acc[mt][nt][rr*2+1] + bias);
            }
        }
    }
}

// ============================================================
// K6: in-place softmax of g_pool over node axis
// ============================================================
__global__ void k_softmax() {
    int bc = blockIdx.x;
    int l = threadIdx.x;
    float* p = g_pool + (size_t)bc*NL;
    float m = -3.4e38f, d = 0.f;
    for (int n = 0; n < Ndim; n++) {
        float v = p[n*Ndim + l];
        float m2 = fmaxf(m, v);
        d = d * __expf(m - m2) + __expf(v - m2);
        m = m2;
    }
    float inv = 1.f / d;
    for (int n = 0; n < Ndim; n++)
        p[n*Ndim + l] = __expf(p[n*Ndim + l] - m) * inv;
}

// ============================================================
extern "C" void kernel_launch(void* const* d_in, const int* in_sizes, int n_in,
                              void* d_out, int out_size) {
    const float* x  = (const float*)d_in[0];
    const float* a  = (const float*)d_in[1];
    const float* We = (const float*)d_in[2];
    const float* be = (const float*)d_in[3];
    const float* Wp = (const float*)d_in[4];
    const float* bp = (const float*)d_in[5];
    float* out  = (float*)d_out;
    float* xnew = out;
    float* anew = out + (size_t)BC*NL;

    void *p_pool, *p_embed, *p_t, *p_Ms, *p_y;
    cudaGetSymbolAddress(&p_pool,  g_pool);
    cudaGetSymbolAddress(&p_embed, g_embed);
    cudaGetSymbolAddress(&p_t,     g_t);
    cudaGetSymbolAddress(&p_Ms,    g_Ms);
    cudaGetSymbolAddress(&p_y,     g_y);

    cudaFuncSetAttribute(k_tgemm2<false>, cudaFuncAttributeMaxDynamicSharedMemorySize, SMEM_TG);
    cudaFuncSetAttribute(k_tgemm2<true>,  cudaFuncAttributeMaxDynamicSharedMemorySize, SMEM_TG);

    k_norm_adj<<<Ndim, Ndim>>>(a);
    k_prep<<<dim3(5, 5), 64>>>();
    k_wcprep<<<(64*96 + 255)/256, 256>>>(We, Wp);

    // ystack = Mstack @ x : M=320 (2 m-tiles), A shared, B batched
    k_tgemm2<false><<<dim3(BC, 2), 320, SMEM_TG>>>(
        (const float*)p_Ms, 0, Ndim, x, NL, Ndim, (float*)p_y, 2*NL, Ndim);

    // channel mix -> embed, pool
    k_mix_t<<<dim3(NL/64, Bdim), 128>>>(x, be, bp);

    k_softmax<<<BC, Ndim>>>();

    // x_new = s^T @ embed : A = s stored [K=n][M=l]
    k_tgemm2<true><<<dim3(BC, 1), 320, SMEM_TG>>>(
        (const float*)p_pool, NL, Ndim, (const float*)p_embed, NL, Ndim,
        xnew, NL, Ndim);

    // t = s @ a  (B shared)
    k_tgemm2<false><<<dim3(BC, 1), 320, SMEM_TG>>>(
        (const float*)p_pool, NL, Ndim, a, 0, Ndim, (float*)p_t, NL, Ndim);

    // a_new = t @ s
    k_tgemm2<false><<<dim3(BC, 1), 320, SMEM_TG>>>(
        (const float*)p_t, NL, Ndim, (const float*)p_pool, NL, Ndim,
        anew, NL, Ndim);
}

// round 5
// speedup vs baseline: 3.4326x; 1.0716x over previous
#include <cuda_runtime.h>
#include <cstdint>

#define Bdim 32
#define Ndim 160
#define NL 25600           // 160*160
#define BC 1024            // 32*32
#define ALPHA 0.05f
#define OMA 0.95f

// ---- scratch (__device__ globals; no allocations) ----
__device__ float g_A1[Ndim*Ndim];
__device__ float g_A2[Ndim*Ndim];
__device__ float g_Ms[2*Ndim*Ndim];        // stacked [320][160]
__device__ float g_Wc[64*96];              // folded weights [o][k]
__device__ float g_y[(size_t)BC*2*NL];     // per bc: [320][160]
__device__ float g_embed[(size_t)BC*NL];
__device__ float g_pool [(size_t)BC*NL];   // becomes s after softmax
__device__ float g_t    [(size_t)BC*NL];   // s @ a

// ---------- tf32 helpers ----------
__device__ __forceinline__ uint32_t f2tf(float v) {
    uint32_t r; asm("cvt.rna.tf32.f32 %0, %1;" : "=r"(r) : "f"(v)); return r;
}
__device__ __forceinline__ void split2(float v, uint32_t& h, uint32_t& l) {
    h = f2tf(v);
    l = f2tf(v - __uint_as_float(h));
}
__device__ __forceinline__ void mma8(float* c, const uint32_t* a, const uint32_t* b) {
    asm volatile(
        "mma.sync.aligned.m16n8k8.row.col.f32.tf32.tf32.f32 "
        "{%0,%1,%2,%3}, {%4,%5,%6,%7}, {%8,%9}, {%0,%1,%2,%3};"
        : "+f"(c[0]), "+f"(c[1]), "+f"(c[2]), "+f"(c[3])
        : "r"(a[0]), "r"(a[1]), "r"(a[2]), "r"(a[3]), "r"(b[0]), "r"(b[1]));
}
// ---------- cp.async helpers ----------
__device__ __forceinline__ void cp16(uint32_t saddr, const float* gptr) {
    asm volatile("cp.async.cg.shared.global [%0], [%1], 16;" :: "r"(saddr), "l"(gptr));
}
#define CP_COMMIT() asm volatile("cp.async.commit_group;")
template<int N> __device__ __forceinline__ void cp_wait() {
    asm volatile("cp.async.wait_group %0;" :: "n"(N));
}

// ============================================================
// K1: row-normalized (a+I) and (a^T+I)
// ============================================================
__global__ void k_norm_adj(const float* __restrict__ a) {
    int v = blockIdx.x;
    int t = threadIdx.x;
    __shared__ float s1[Ndim], s2[Ndim];
    __shared__ float r1, r2;
    float av = a[v*Ndim + t];
    float aw = a[t*Ndim + v];
    s1[t] = av; s2[t] = aw;
    __syncthreads();
    if (t == 0) {
        float x1 = 0.f, x2 = 0.f;
        for (int i = 0; i < Ndim; i++) { x1 += s1[i]; x2 += s2[i]; }
        r1 = x1 + 1.f; r2 = x2 + 1.f;
    }
    __syncthreads();
    float diag = (t == v) ? 1.f : 0.f;
    g_A1[v*Ndim + t] = (av + diag) / r1;
    g_A2[v*Ndim + t] = (aw + diag) / r2;
}

// ============================================================
// K2: Mstack rows v = (1-a)(A1+A2); rows 160+v = a(1-a)(A1+A2)+(1-a)^2(A1^2+A2^2)
// ============================================================
__global__ void k_prep() {
    __shared__ float As1[32][36], As2[32][36], Bs1[32][36], Bs2[32][36];
    int tid = threadIdx.x;
    int tx = tid & 7, ty = tid >> 3;
    int bi = blockIdx.y, bj = blockIdx.x;
    float c1[4][4] = {}, c2[4][4] = {};
    for (int kt = 0; kt < 5; kt++) {
        #pragma unroll
        for (int it = 0; it < 4; it++) {
            int g = tid + it*64;
            int m = g >> 3, k4 = g & 7;
            float4 v1 = *(const float4*)&g_A1[(bi*32+m)*Ndim + kt*32 + k4*4];
            float4 v2 = *(const float4*)&g_A2[(bi*32+m)*Ndim + kt*32 + k4*4];
            As1[k4*4+0][m] = v1.x; As1[k4*4+1][m] = v1.y;
            As1[k4*4+2][m] = v1.z; As1[k4*4+3][m] = v1.w;
            As2[k4*4+0][m] = v2.x; As2[k4*4+1][m] = v2.y;
            As2[k4*4+2][m] = v2.z; As2[k4*4+3][m] = v2.w;
            int r = g >> 3, c4 = g & 7;
            *(float4*)&Bs1[r][c4*4] = *(const float4*)&g_A1[(kt*32+r)*Ndim + bj*32 + c4*4];
            *(float4*)&Bs2[r][c4*4] = *(const float4*)&g_A2[(kt*32+r)*Ndim + bj*32 + c4*4];
        }
        __syncthreads();
        #pragma unroll
        for (int k = 0; k < 32; k++) {
            float4 a1 = *(const float4*)&As1[k][ty*4];
            float4 a2 = *(const float4*)&As2[k][ty*4];
            float4 b1 = *(const float4*)&Bs1[k][tx*4];
            float4 b2 = *(const float4*)&Bs2[k][tx*4];
            float aa1[4] = {a1.x,a1.y,a1.z,a1.w}, aa2[4] = {a2.x,a2.y,a2.z,a2.w};
            float bb1[4] = {b1.x,b1.y,b1.z,b1.w}, bb2[4] = {b2.x,b2.y,b2.z,b2.w};
            #pragma unroll
            for (int i = 0; i < 4; i++)
            #pragma unroll
            for (int j = 0; j < 4; j++) {
                c1[i][j] += aa1[i]*bb1[j];
                c2[i][j] += aa2[i]*bb2[j];
            }
        }
        __syncthreads();
    }
    #pragma unroll
    for (int i = 0; i < 4; i++) {
        int row = bi*32 + ty*4 + i;
        int col = bj*32 + tx*4;
        float4 a1 = *(const float4*)&g_A1[row*Ndim + col];
        float4 a2 = *(const float4*)&g_A2[row*Ndim + col];
        float s0 = a1.x + a2.x, s1v = a1.y + a2.y, s2v = a1.z + a2.z, s3 = a1.w + a2.w;
        *(float4*)&g_Ms[row*Ndim + col] = make_float4(OMA*s0, OMA*s1v, OMA*s2v, OMA*s3);
        *(float4*)&g_Ms[(160+row)*Ndim + col] = make_float4(
            ALPHA*OMA*s0  + OMA*OMA*(c1[i][0]+c2[i][0]),
            ALPHA*OMA*s1v + OMA*OMA*(c1[i][1]+c2[i][1]),
            ALPHA*OMA*s2v + OMA*OMA*(c1[i][2]+c2[i][2]),
            ALPHA*OMA*s3  + OMA*OMA*(c1[i][3]+c2[i][3]));
    }
}

// ============================================================
// K3: folded weights Wc[o][k]
// ============================================================
__global__ void k_wcprep(const float* __restrict__ We, const float* __restrict__ Wp) {
    int idx = blockIdx.x*256 + threadIdx.x;
    if (idx >= 64*96) return;
    int o = idx / 96, k = idx % 96;
    const float* W = (o < 32) ? We : Wp;
    int oo = o & 31;
    float v;
    if (k < 32) v = 2.f*W[oo*96 + k] + 2.f*ALPHA*(W[oo*96 + k + 32] + W[oo*96 + k + 64]);
    else        v = W[oo*96 + k];
    g_Wc[o*96 + k] = v;
}

// ============================================================
// K4: batched TF32 split GEMM, CTA = 160x160 tile, cp.async double-buffered,
//     raw fp32 in smem, hi/lo split at consume.
// 320 threads, warps 2(M)x5(N), warp tile 80x32, K=160 in 5 chunks of 32.
// TA=false: A [M][K] -> smem [m][36]; TA=true: A [K][M] -> smem [k][168].
// B [K][N] -> smem [k][168].
// ============================================================
template<bool TA>
struct TG {
    static const int AS = TA ? 32*168 : 160*36;
    static const int BS = 32*168;
    static const int STG = AS + BS;
    static const int SMEM = STG*2*4;
};

template<bool TA>
__global__ void __launch_bounds__(320, 1) k_tgemm3(
    const float* __restrict__ A, long sA, int lda,
    const float* __restrict__ B, long sB, int ldb,
    float* __restrict__ C, long sC, int ldc)
{
    extern __shared__ float sm[];
    const int AS = TG<TA>::AS, STG = TG<TA>::STG;
    uint32_t sb = (uint32_t)__cvta_generic_to_shared(sm);

    int bc = blockIdx.x;
    int m0 = blockIdx.y * 160;
    const float* Ab = A + (size_t)bc*sA;
    const float* Bb = B + (size_t)bc*sB;
    float*       Cb = C + (size_t)bc*sC;

    int tid = threadIdx.x, lane = tid & 31, wid = tid >> 5;
    int wmi = wid & 1, wni = wid >> 1;
    int g = lane >> 2, t = lane & 3;

    float acc[5][4][4] = {};

    // ---- stage issuer ----
    auto stage = [&](int kt, int st) {
        uint32_t base = sb + (uint32_t)(st*STG)*4;
        if (TA) {
            #pragma unroll
            for (int i = 0; i < 4; i++) {
                int s = tid + i*320;
                int k = s / 40, m4 = (s % 40)*4;
                cp16(base + (uint32_t)(k*168 + m4)*4, &Ab[(size_t)(kt+k)*lda + m0 + m4]);
            }
        } else {
            #pragma unroll
            for (int i = 0; i < 4; i++) {
                int s = tid + i*320;
                int m = s >> 3, k4 = (s & 7)*4;
                cp16(base + (uint32_t)(m*36 + k4)*4, &Ab[(size_t)(m0+m)*lda + kt + k4]);
            }
        }
        uint32_t bbase = base + (uint32_t)AS*4;
        #pragma unroll
        for (int i = 0; i < 4; i++) {
            int s = tid + i*320;
            int k = s / 40, n4 = (s % 40)*4;
            cp16(bbase + (uint32_t)(k*168 + n4)*4, &Bb[(size_t)(kt+k)*ldb + n4]);
        }
        CP_COMMIT();
    };

    stage(0, 0);
    #pragma unroll
    for (int it = 0; it < 5; it++) {
        if (it + 1 < 5) { stage((it+1)*32, (it+1)&1); cp_wait<1>(); }
        else            { cp_wait<0>(); }
        __syncthreads();
        const float* As = sm + (it&1)*STG;
        const float* Bs = As + AS;
        #pragma unroll
        for (int kk = 0; kk < 32; kk += 8) {
            uint32_t Ah[5][4], Al[5][4];
            #pragma unroll
            for (int mt = 0; mt < 5; mt++) {
                int mr = wmi*80 + mt*16 + g;
                float r0, r1, r2, r3;
                if (TA) {
                    r0 = As[(kk+t)*168 + mr];     r1 = As[(kk+t)*168 + mr + 8];
                    r2 = As[(kk+t+4)*168 + mr];   r3 = As[(kk+t+4)*168 + mr + 8];
                } else {
                    r0 = As[mr*36 + kk + t];      r1 = As[(mr+8)*36 + kk + t];
                    r2 = As[mr*36 + kk + t + 4];  r3 = As[(mr+8)*36 + kk + t + 4];
                }
                split2(r0, Ah[mt][0], Al[mt][0]);
                split2(r1, Ah[mt][1], Al[mt][1]);
                split2(r2, Ah[mt][2], Al[mt][2]);
                split2(r3, Ah[mt][3], Al[mt][3]);
            }
            #pragma unroll
            for (int nt = 0; nt < 4; nt++) {
                int nc = wni*32 + nt*8 + g;
                uint32_t bh[2], bl[2];
                split2(Bs[(kk+t)*168 + nc],   bh[0], bl[0]);
                split2(Bs[(kk+t+4)*168 + nc], bh[1], bl[1]);
                #pragma unroll
                for (int mt = 0; mt < 5; mt++) {
                    mma8(acc[mt][nt], Ah[mt], bh);
                    mma8(acc[mt][nt], Ah[mt], bl);
                    mma8(acc[mt][nt], Al[mt], bh);
                }
            }
        }
        __syncthreads();
    }
    #pragma unroll
    for (int mt = 0; mt < 5; mt++) {
        int r0 = m0 + wmi*80 + mt*16 + g;
        #pragma unroll
        for (int nt = 0; nt < 4; nt++) {
            int c0 = wni*32 + nt*8 + 2*t;
            *(float2*)&Cb[(size_t)r0*ldc + c0] =
                make_float2(acc[mt][nt][0], acc[mt][nt][1]);
            *(float2*)&Cb[(size_t)(r0+8)*ldc + c0] =
                make_float2(acc[mt][nt][2], acc[mt][nt][3]);
        }
    }
}

// ============================================================
// K5: channel mix. CTA = 64(out ch) x 160(points), K=96 in 3 chunks.
// 320 threads, warps 2(M)x5(N), warp tile 32x32. cp.async double-buffered.
// A = g_Wc chunk [64][36]; B = gathered rows [32][168].
// ============================================================
#define MIX_AS (64*36)
#define MIX_BS (32*168)
#define MIX_STG (MIX_AS + MIX_BS)
#define MIX_SMEM (MIX_STG*2*4)

__global__ void __launch_bounds__(320, 1) k_mix2(
    const float* __restrict__ x,
    const float* __restrict__ be, const float* __restrict__ bp)
{
    extern __shared__ float sm[];
    uint32_t sb = (uint32_t)__cvta_generic_to_shared(sm);
    int b  = blockIdx.y;
    int p0 = blockIdx.x * 160;
    int tid = threadIdx.x, lane = tid & 31, wid = tid >> 5;
    int wmi = wid & 1, wni = wid >> 1;
    int g = lane >> 2, t = lane & 3;

    float acc[2][4][4] = {};

    auto stage = [&](int ktc, int st) {
        uint32_t base = sb + (uint32_t)(st*MIX_STG)*4;
        #pragma unroll
        for (int i = 0; i < 2; i++) {
            int s = tid + i*320;
            if (s < 512) {
                int m = s >> 3, k4 = (s & 7)*4;
                cp16(base + (uint32_t)(m*36 + k4)*4, &g_Wc[m*96 + ktc + k4]);
            }
        }
        uint32_t bbase = base + (uint32_t)MIX_AS*4;
        #pragma unroll
        for (int i = 0; i < 4; i++) {
            int s = tid + i*320;
            int k = s / 40, n4 = (s % 40)*4;
            int kg = ktc + k;
            int c = kg & 31;
            const float* src;
            if (kg < 32)      src = x   + ((size_t)b*32 + c)*NL;
            else if (kg < 64) src = g_y + ((size_t)b*32 + c)*(2*NL);
            else              src = g_y + ((size_t)b*32 + c)*(2*NL) + NL;
            cp16(bbase + (uint32_t)(k*168 + n4)*4, &src[p0 + n4]);
        }
        CP_COMMIT();
    };

    stage(0, 0);
    #pragma unroll
    for (int it = 0; it < 3; it++) {
        if (it + 1 < 3) { stage((it+1)*32, (it+1)&1); cp_wait<1>(); }
        else            { cp_wait<0>(); }
        __syncthreads();
        const float* As = sm + (it&1)*MIX_STG;
        const float* Bs = As + MIX_AS;
        #pragma unroll
        for (int kk = 0; kk < 32; kk += 8) {
            uint32_t Ah[2][4], Al[2][4];
            #pragma unroll
            for (int mt = 0; mt < 2; mt++) {
                int mr = wmi*32 + mt*16 + g;
                split2(As[mr*36 + kk + t],         Ah[mt][0], Al[mt][0]);
                split2(As[(mr+8)*36 + kk + t],     Ah[mt][1], Al[mt][1]);
                split2(As[mr*36 + kk + t + 4],     Ah[mt][2], Al[mt][2]);
                split2(As[(mr+8)*36 + kk + t + 4], Ah[mt][3], Al[mt][3]);
            }
            #pragma unroll
            for (int nt = 0; nt < 4; nt++) {
                int nc = wni*32 + nt*8 + g;
                uint32_t bh[2], bl[2];
                split2(Bs[(kk+t)*168 + nc],   bh[0], bl[0]);
                split2(Bs[(kk+t+4)*168 + nc], bh[1], bl[1]);
                #pragma unroll
                for (int mt = 0; mt < 2; mt++) {
                    mma8(acc[mt][nt], Ah[mt], bh);
                    mma8(acc[mt][nt], Ah[mt], bl);
                    mma8(acc[mt][nt], Al[mt], bh);
                }
            }
        }
        __syncthreads();
    }
    #pragma unroll
    for (int mt = 0; mt < 2; mt++) {
        #pragma unroll
        for (int rr = 0; rr < 2; rr++) {
            int o = wmi*32 + mt*16 + g + rr*8;
            float bias = 2.f * ((o < 32) ? be[o] : bp[o-32]);
            float* dst = (o < 32) ? g_embed : g_pool;
            size_t base = ((size_t)b*32 + (o & 31))*NL + p0;
            #pragma unroll
            for (int nt = 0; nt < 4; nt++) {
                int c0 = wni*32 + nt*8 + 2*t;
                *(float2*)&dst[base + c0] =
                    make_float2(acc[mt][nt][rr*2+0] + bias, acc[mt][nt][rr*2+1] + bias);
            }
        }
    }
}

// ============================================================
// K6: in-place softmax of g_pool over node axis
// ============================================================
__global__ void k_softmax() {
    int bc = blockIdx.x;
    int l = threadIdx.x;
    float* p = g_pool + (size_t)bc*NL;
    float m = -3.4e38f, d = 0.f;
    for (int n = 0; n < Ndim; n++) {
        float v = p[n*Ndim + l];
        float m2 = fmaxf(m, v);
        d = d * __expf(m - m2) + __expf(v - m2);
        m = m2;
    }
    float inv = 1.f / d;
    for (int n = 0; n < Ndim; n++)
        p[n*Ndim + l] = __expf(p[n*Ndim + l] - m) * inv;
}

// ============================================================
extern "C" void kernel_launch(void* const* d_in, const int* in_sizes, int n_in,
                              void* d_out, int out_size) {
    const float* x  = (const float*)d_in[0];
    const float* a  = (const float*)d_in[1];
    const float* We = (const float*)d_in[2];
    const float* be = (const float*)d_in[3];
    const float* Wp = (const float*)d_in[4];
    const float* bp = (const float*)d_in[5];
    float* out  = (float*)d_out;
    float* xnew = out;
    float* anew = out + (size_t)BC*NL;

    void *p_pool, *p_embed, *p_t, *p_Ms, *p_y;
    cudaGetSymbolAddress(&p_pool,  g_pool);
    cudaGetSymbolAddress(&p_embed, g_embed);
    cudaGetSymbolAddress(&p_t,     g_t);
    cudaGetSymbolAddress(&p_Ms,    g_Ms);
    cudaGetSymbolAddress(&p_y,     g_y);

    cudaFuncSetAttribute(k_tgemm3<false>, cudaFuncAttributeMaxDynamicSharedMemorySize, TG<false>::SMEM);
    cudaFuncSetAttribute(k_tgemm3<true>,  cudaFuncAttributeMaxDynamicSharedMemorySize, TG<true>::SMEM);
    cudaFuncSetAttribute(k_mix2, cudaFuncAttributeMaxDynamicSharedMemorySize, MIX_SMEM);

    k_norm_adj<<<Ndim, Ndim>>>(a);
    k_prep<<<dim3(5, 5), 64>>>();
    k_wcprep<<<(64*96 + 255)/256, 256>>>(We, Wp);

    // ystack = Mstack @ x : M=320 (2 m-tiles), A shared, B batched
    k_tgemm3<false><<<dim3(BC, 2), 320, TG<false>::SMEM>>>(
        (const float*)p_Ms, 0, Ndim, x, NL, Ndim, (float*)p_y, 2*NL, Ndim);

    // channel mix -> embed, pool
    k_mix2<<<dim3(NL/160, Bdim), 320, MIX_SMEM>>>(x, be, bp);

    k_softmax<<<BC, Ndim>>>();

    // x_new = s^T @ embed : A = s stored [K=n][M=l]
    k_tgemm3<true><<<dim3(BC, 1), 320, TG<true>::SMEM>>>(
        (const float*)p_pool, NL, Ndim, (const float*)p_embed, NL, Ndim,
        xnew, NL, Ndim);

    // t = s @ a  (B shared)
    k_tgemm3<false><<<dim3(BC, 1), 320, TG<false>::SMEM>>>(
        (const float*)p_pool, NL, Ndim, a, 0, Ndim, (float*)p_t, NL, Ndim);

    // a_new = t @ s
    k_tgemm3<false><<<dim3(BC, 1), 320, TG<false>::SMEM>>>(
        (const float*)p_t, NL, Ndim, (const float*)p_pool, NL, Ndim,
        anew, NL, Ndim);
}

// round 6
// speedup vs baseline: 3.5678x; 1.0394x over previous
#include <cuda_runtime.h>
#include <cstdint>

#define Bdim 32
#define Ndim 160
#define NL 25600           // 160*160
#define BC 1024            // 32*32
#define ALPHA 0.05f
#define OMA 0.95f

// ---- scratch (__device__ globals; no allocations) ----
__device__ float g_A1[Ndim*Ndim];
__device__ float g_A2[Ndim*Ndim];
__device__ float g_Ms[2*Ndim*Ndim];        // stacked [320][160]
__device__ float g_Wc[64*96];              // folded weights [o][k]
__device__ float g_y[(size_t)BC*2*NL];     // per bc: [320][160]
__device__ float g_embed[(size_t)BC*NL];
__device__ float g_pool [(size_t)BC*NL];   // becomes s after softmax
__device__ float g_t    [(size_t)BC*NL];   // s @ a

// ---------- tf32 helpers ----------
__device__ __forceinline__ uint32_t f2tf(float v) {
    uint32_t r; asm("cvt.rna.tf32.f32 %0, %1;" : "=r"(r) : "f"(v)); return r;
}
__device__ __forceinline__ void split2(float v, uint32_t& h, uint32_t& l) {
    h = f2tf(v);
    l = f2tf(v - __uint_as_float(h));
}
__device__ __forceinline__ void mma8(float* c, const uint32_t* a, const uint32_t* b) {
    asm volatile(
        "mma.sync.aligned.m16n8k8.row.col.f32.tf32.tf32.f32 "
        "{%0,%1,%2,%3}, {%4,%5,%6,%7}, {%8,%9}, {%0,%1,%2,%3};"
        : "+f"(c[0]), "+f"(c[1]), "+f"(c[2]), "+f"(c[3])
        : "r"(a[0]), "r"(a[1]), "r"(a[2]), "r"(a[3]), "r"(b[0]), "r"(b[1]));
}
// ---------- cp.async helpers ----------
__device__ __forceinline__ void cp16(uint32_t saddr, const float* gptr) {
    asm volatile("cp.async.cg.shared.global [%0], [%1], 16;" :: "r"(saddr), "l"(gptr));
}
#define CP_COMMIT() asm volatile("cp.async.commit_group;")
template<int N> __device__ __forceinline__ void cp_wait() {
    asm volatile("cp.async.wait_group %0;" :: "n"(N));
}

// ============================================================
// K1: row-normalized (a+I) and (a^T+I)
// ============================================================
__global__ void k_norm_adj(const float* __restrict__ a) {
    int v = blockIdx.x;
    int t = threadIdx.x;
    __shared__ float s1[Ndim], s2[Ndim];
    __shared__ float r1, r2;
    float av = a[v*Ndim + t];
    float aw = a[t*Ndim + v];
    s1[t] = av; s2[t] = aw;
    __syncthreads();
    if (t == 0) {
        float x1 = 0.f, x2 = 0.f;
        for (int i = 0; i < Ndim; i++) { x1 += s1[i]; x2 += s2[i]; }
        r1 = x1 + 1.f; r2 = x2 + 1.f;
    }
    __syncthreads();
    float diag = (t == v) ? 1.f : 0.f;
    g_A1[v*Ndim + t] = (av + diag) / r1;
    g_A2[v*Ndim + t] = (aw + diag) / r2;
}

// ============================================================
// K2: Mstack rows v = (1-a)(A1+A2); rows 160+v = a(1-a)(A1+A2)+(1-a)^2(A1^2+A2^2)
// ============================================================
__global__ void k_prep() {
    __shared__ float As1[32][36], As2[32][36], Bs1[32][36], Bs2[32][36];
    int tid = threadIdx.x;
    int tx = tid & 7, ty = tid >> 3;
    int bi = blockIdx.y, bj = blockIdx.x;
    float c1[4][4] = {}, c2[4][4] = {};
    for (int kt = 0; kt < 5; kt++) {
        #pragma unroll
        for (int it = 0; it < 4; it++) {
            int g = tid + it*64;
            int m = g >> 3, k4 = g & 7;
            float4 v1 = *(const float4*)&g_A1[(bi*32+m)*Ndim + kt*32 + k4*4];
            float4 v2 = *(const float4*)&g_A2[(bi*32+m)*Ndim + kt*32 + k4*4];
            As1[k4*4+0][m] = v1.x; As1[k4*4+1][m] = v1.y;
            As1[k4*4+2][m] = v1.z; As1[k4*4+3][m] = v1.w;
            As2[k4*4+0][m] = v2.x; As2[k4*4+1][m] = v2.y;
            As2[k4*4+2][m] = v2.z; As2[k4*4+3][m] = v2.w;
            int r = g >> 3, c4 = g & 7;
            *(float4*)&Bs1[r][c4*4] = *(const float4*)&g_A1[(kt*32+r)*Ndim + bj*32 + c4*4];
            *(float4*)&Bs2[r][c4*4] = *(const float4*)&g_A2[(kt*32+r)*Ndim + bj*32 + c4*4];
        }
        __syncthreads();
        #pragma unroll
        for (int k = 0; k < 32; k++) {
            float4 a1 = *(const float4*)&As1[k][ty*4];
            float4 a2 = *(const float4*)&As2[k][ty*4];
            float4 b1 = *(const float4*)&Bs1[k][tx*4];
            float4 b2 = *(const float4*)&Bs2[k][tx*4];
            float aa1[4] = {a1.x,a1.y,a1.z,a1.w}, aa2[4] = {a2.x,a2.y,a2.z,a2.w};
            float bb1[4] = {b1.x,b1.y,b1.z,b1.w}, bb2[4] = {b2.x,b2.y,b2.z,b2.w};
            #pragma unroll
            for (int i = 0; i < 4; i++)
            #pragma unroll
            for (int j = 0; j < 4; j++) {
                c1[i][j] += aa1[i]*bb1[j];
                c2[i][j] += aa2[i]*bb2[j];
            }
        }
        __syncthreads();
    }
    #pragma unroll
    for (int i = 0; i < 4; i++) {
        int row = bi*32 + ty*4 + i;
        int col = bj*32 + tx*4;
        float4 a1 = *(const float4*)&g_A1[row*Ndim + col];
        float4 a2 = *(const float4*)&g_A2[row*Ndim + col];
        float s0 = a1.x + a2.x, s1v = a1.y + a2.y, s2v = a1.z + a2.z, s3 = a1.w + a2.w;
        *(float4*)&g_Ms[row*Ndim + col] = make_float4(OMA*s0, OMA*s1v, OMA*s2v, OMA*s3);
        *(float4*)&g_Ms[(160+row)*Ndim + col] = make_float4(
            ALPHA*OMA*s0  + OMA*OMA*(c1[i][0]+c2[i][0]),
            ALPHA*OMA*s1v + OMA*OMA*(c1[i][1]+c2[i][1]),
            ALPHA*OMA*s2v + OMA*OMA*(c1[i][2]+c2[i][2]),
            ALPHA*OMA*s3  + OMA*OMA*(c1[i][3]+c2[i][3]));
    }
}

// ============================================================
// K3: folded weights Wc[o][k]
// ============================================================
__global__ void k_wcprep(const float* __restrict__ We, const float* __restrict__ Wp) {
    int idx = blockIdx.x*256 + threadIdx.x;
    if (idx >= 64*96) return;
    int o = idx / 96, k = idx % 96;
    const float* W = (o < 32) ? We : Wp;
    int oo = o & 31;
    float v;
    if (k < 32) v = 2.f*W[oo*96 + k] + 2.f*ALPHA*(W[oo*96 + k + 32] + W[oo*96 + k + 64]);
    else        v = W[oo*96 + k];
    g_Wc[o*96 + k] = v;
}

// ============================================================
// K4: batched TF32 split GEMM, CTA = 160(M) x 80(N) tile, 2 CTAs/SM.
// 320 threads, warps 5(M) x 2(N), warp tile 32x40. K in chunks of 32,
// cp.async double-buffered, raw fp32 smem, hi/lo split at consume.
// TA=false: A [M][K] -> smem [m][36]; TA=true: A [K][M] -> smem [k][168].
// B [K][N-tile 80] -> smem [k][88].
// grid: (bc, n-tile, m-tile)
// ============================================================
template<bool TA>
struct TG {
    static const int AS = TA ? 32*168 : 160*36;
    static const int BS = 32*88;
    static const int STG = AS + BS;
    static const int SMEM = STG*2*4;
};

template<bool TA>
__global__ void __launch_bounds__(320, 2) k_tgemm4(
    const float* __restrict__ A, long sA, int lda,
    const float* __restrict__ B, long sB, int ldb,
    float* __restrict__ C, long sC, int ldc)
{
    extern __shared__ float sm[];
    const int AS = TG<TA>::AS, STG = TG<TA>::STG;
    uint32_t sb = (uint32_t)__cvta_generic_to_shared(sm);

    int bc = blockIdx.x;
    int n0 = blockIdx.y * 80;
    int m0 = blockIdx.z * 160;
    const float* Ab = A + (size_t)bc*sA;
    const float* Bb = B + (size_t)bc*sB;
    float*       Cb = C + (size_t)bc*sC;

    int tid = threadIdx.x, lane = tid & 31, wid = tid >> 5;
    int wmi = wid % 5, wni = wid / 5;        // 5(M) x 2(N)
    int g = lane >> 2, t = lane & 3;

    float acc[2][5][4] = {};

    auto stage = [&](int kt, int st) {
        uint32_t base = sb + (uint32_t)(st*STG)*4;
        if (TA) {
            // A [k][168]: 32 x 160 floats = 1280 float4 / 320 thr = 4
            #pragma unroll
            for (int i = 0; i < 4; i++) {
                int s = tid + i*320;
                int k = s / 40, m4 = (s % 40)*4;
                cp16(base + (uint32_t)(k*168 + m4)*4, &Ab[(size_t)(kt+k)*lda + m0 + m4]);
            }
        } else {
            // A [m][36]: 160 x 32 floats = 1280 float4 / 320 thr = 4
            #pragma unroll
            for (int i = 0; i < 4; i++) {
                int s = tid + i*320;
                int m = s >> 3, k4 = (s & 7)*4;
                cp16(base + (uint32_t)(m*36 + k4)*4, &Ab[(size_t)(m0+m)*lda + kt + k4]);
            }
        }
        // B [k][88]: 32 x 80 floats = 640 float4 / 320 thr = 2
        uint32_t bbase = base + (uint32_t)AS*4;
        #pragma unroll
        for (int i = 0; i < 2; i++) {
            int s = tid + i*320;
            int k = s / 20, n4 = (s % 20)*4;
            cp16(bbase + (uint32_t)(k*88 + n4)*4, &Bb[(size_t)(kt+k)*ldb + n0 + n4]);
        }
        CP_COMMIT();
    };

    stage(0, 0);
    #pragma unroll
    for (int it = 0; it < 5; it++) {
        if (it + 1 < 5) { stage((it+1)*32, (it+1)&1); cp_wait<1>(); }
        else            { cp_wait<0>(); }
        __syncthreads();
        const float* As = sm + (it&1)*STG;
        const float* Bs = As + AS;
        #pragma unroll
        for (int kk = 0; kk < 32; kk += 8) {
            uint32_t Ah[2][4], Al[2][4];
            #pragma unroll
            for (int mt = 0; mt < 2; mt++) {
                int mr = wmi*32 + mt*16 + g;
                float r0, r1, r2, r3;
                if (TA) {
                    r0 = As[(kk+t)*168 + mr];     r1 = As[(kk+t)*168 + mr + 8];
                    r2 = As[(kk+t+4)*168 + mr];   r3 = As[(kk+t+4)*168 + mr + 8];
                } else {
                    r0 = As[mr*36 + kk + t];      r1 = As[(mr+8)*36 + kk + t];
                    r2 = As[mr*36 + kk + t + 4];  r3 = As[(mr+8)*36 + kk + t + 4];
                }
                split2(r0, Ah[mt][0], Al[mt][0]);
                split2(r1, Ah[mt][1], Al[mt][1]);
                split2(r2, Ah[mt][2], Al[mt][2]);
                split2(r3, Ah[mt][3], Al[mt][3]);
            }
            #pragma unroll
            for (int nt = 0; nt < 5; nt++) {
                int nc = wni*40 + nt*8 + g;
                uint32_t bh[2], bl[2];
                split2(Bs[(kk+t)*88 + nc],   bh[0], bl[0]);
                split2(Bs[(kk+t+4)*88 + nc], bh[1], bl[1]);
                #pragma unroll
                for (int mt = 0; mt < 2; mt++) {
                    mma8(acc[mt][nt], Ah[mt], bh);
                    mma8(acc[mt][nt], Ah[mt], bl);
                    mma8(acc[mt][nt], Al[mt], bh);
                }
            }
        }
        __syncthreads();
    }
    #pragma unroll
    for (int mt = 0; mt < 2; mt++) {
        int r0 = m0 + wmi*32 + mt*16 + g;
        #pragma unroll
        for (int nt = 0; nt < 5; nt++) {
            int c0 = n0 + wni*40 + nt*8 + 2*t;
            *(float2*)&Cb[(size_t)r0*ldc + c0] =
                make_float2(acc[mt][nt][0], acc[mt][nt][1]);
            *(float2*)&Cb[(size_t)(r0+8)*ldc + c0] =
                make_float2(acc[mt][nt][2], acc[mt][nt][3]);
        }
    }
}

// ============================================================
// K5: channel mix. CTA = 64(out ch) x 160(points), K=96 in 3 chunks.
// 320 threads, warps 2(M)x5(N), warp tile 32x32. cp.async double-buffered.
// ============================================================
#define MIX_AS (64*36)
#define MIX_BS (32*168)
#define MIX_STG (MIX_AS + MIX_BS)
#define MIX_SMEM (MIX_STG*2*4)

__global__ void __launch_bounds__(320, 2) k_mix2(
    const float* __restrict__ x,
    const float* __restrict__ be, const float* __restrict__ bp)
{
    extern __shared__ float sm[];
    uint32_t sb = (uint32_t)__cvta_generic_to_shared(sm);
    int b  = blockIdx.y;
    int p0 = blockIdx.x * 160;
    int tid = threadIdx.x, lane = tid & 31, wid = tid >> 5;
    int wmi = wid & 1, wni = wid >> 1;
    int g = lane >> 2, t = lane & 3;

    float acc[2][4][4] = {};

    auto stage = [&](int ktc, int st) {
        uint32_t base = sb + (uint32_t)(st*MIX_STG)*4;
        #pragma unroll
        for (int i = 0; i < 2; i++) {
            int s = tid + i*320;
            if (s < 512) {
                int m = s >> 3, k4 = (s & 7)*4;
                cp16(base + (uint32_t)(m*36 + k4)*4, &g_Wc[m*96 + ktc + k4]);
            }
        }
        uint32_t bbase = base + (uint32_t)MIX_AS*4;
        #pragma unroll
        for (int i = 0; i < 4; i++) {
            int s = tid + i*320;
            int k = s / 40, n4 = (s % 40)*4;
            int kg = ktc + k;
            int c = kg & 31;
            const float* src;
            if (kg < 32)      src = x   + ((size_t)b*32 + c)*NL;
            else if (kg < 64) src = g_y + ((size_t)b*32 + c)*(2*NL);
            else              src = g_y + ((size_t)b*32 + c)*(2*NL) + NL;
            cp16(bbase + (uint32_t)(k*168 + n4)*4, &src[p0 + n4]);
        }
        CP_COMMIT();
    };

    stage(0, 0);
    #pragma unroll
    for (int it = 0; it < 3; it++) {
        if (it + 1 < 3) { stage((it+1)*32, (it+1)&1); cp_wait<1>(); }
        else            { cp_wait<0>(); }
        __syncthreads();
        const float* As = sm + (it&1)*MIX_STG;
        const float* Bs = As + MIX_AS;
        #pragma unroll
        for (int kk = 0; kk < 32; kk += 8) {
            uint32_t Ah[2][4], Al[2][4];
            #pragma unroll
            for (int mt = 0; mt < 2; mt++) {
                int mr = wmi*32 + mt*16 + g;
                split2(As[mr*36 + kk + t],         Ah[mt][0], Al[mt][0]);
                split2(As[(mr+8)*36 + kk + t],     Ah[mt][1], Al[mt][1]);
                split2(As[mr*36 + kk + t + 4],     Ah[mt][2], Al[mt][2]);
                split2(As[(mr+8)*36 + kk + t + 4], Ah[mt][3], Al[mt][3]);
            }
            #pragma unroll
            for (int nt = 0; nt < 4; nt++) {
                int nc = wni*32 + nt*8 + g;
                uint32_t bh[2], bl[2];
                split2(Bs[(kk+t)*168 + nc],   bh[0], bl[0]);
                split2(Bs[(kk+t+4)*168 + nc], bh[1], bl[1]);
                #pragma unroll
                for (int mt = 0; mt < 2; mt++) {
                    mma8(acc[mt][nt], Ah[mt], bh);
                    mma8(acc[mt][nt], Ah[mt], bl);
                    mma8(acc[mt][nt], Al[mt], bh);
                }
            }
        }
        __syncthreads();
    }
    #pragma unroll
    for (int mt = 0; mt < 2; mt++) {
        #pragma unroll
        for (int rr = 0; rr < 2; rr++) {
            int o = wmi*32 + mt*16 + g + rr*8;
            float bias = 2.f * ((o < 32) ? be[o] : bp[o-32]);
            float* dst = (o < 32) ? g_embed : g_pool;
            size_t base = ((size_t)b*32 + (o & 31))*NL + p0;
            #pragma unroll
            for (int nt = 0; nt < 4; nt++) {
                int c0 = wni*32 + nt*8 + 2*t;
                *(float2*)&dst[base + c0] =
                    make_float2(acc[mt][nt][rr*2+0] + bias, acc[mt][nt][rr*2+1] + bias);
            }
        }
    }
}

// ============================================================
// K6: in-place softmax of g_pool over node axis
// ============================================================
__global__ void k_softmax() {
    int bc = blockIdx.x;
    int l = threadIdx.x;
    float* p = g_pool + (size_t)bc*NL;
    float m = -3.4e38f, d = 0.f;
    for (int n = 0; n < Ndim; n++) {
        float v = p[n*Ndim + l];
        float m2 = fmaxf(m, v);
        d = d * __expf(m - m2) + __expf(v - m2);
        m = m2;
    }
    float inv = 1.f / d;
    for (int n = 0; n < Ndim; n++)
        p[n*Ndim + l] = __expf(p[n*Ndim + l] - m) * inv;
}

// ============================================================
extern "C" void kernel_launch(void* const* d_in, const int* in_sizes, int n_in,
                              void* d_out, int out_size) {
    const float* x  = (const float*)d_in[0];
    const float* a  = (const float*)d_in[1];
    const float* We = (const float*)d_in[2];
    const float* be = (const float*)d_in[3];
    const float* Wp = (const float*)d_in[4];
    const float* bp = (const float*)d_in[5];
    float* out  = (float*)d_out;
    float* xnew = out;
    float* anew = out + (size_t)BC*NL;

    void *p_pool, *p_embed, *p_t, *p_Ms, *p_y;
    cudaGetSymbolAddress(&p_pool,  g_pool);
    cudaGetSymbolAddress(&p_embed, g_embed);
    cudaGetSymbolAddress(&p_t,     g_t);
    cudaGetSymbolAddress(&p_Ms,    g_Ms);
    cudaGetSymbolAddress(&p_y,     g_y);

    cudaFuncSetAttribute(k_tgemm4<false>, cudaFuncAttributeMaxDynamicSharedMemorySize, TG<false>::SMEM);
    cudaFuncSetAttribute(k_tgemm4<true>,  cudaFuncAttributeMaxDynamicSharedMemorySize, TG<true>::SMEM);
    cudaFuncSetAttribute(k_mix2, cudaFuncAttributeMaxDynamicSharedMemorySize, MIX_SMEM);

    k_norm_adj<<<Ndim, Ndim>>>(a);
    k_prep<<<dim3(5, 5), 64>>>();
    k_wcprep<<<(64*96 + 255)/256, 256>>>(We, Wp);

    // ystack = Mstack @ x : M=320 (2 m-tiles), N=160 (2 n-tiles)
    k_tgemm4<false><<<dim3(BC, 2, 2), 320, TG<false>::SMEM>>>(
        (const float*)p_Ms, 0, Ndim, x, NL, Ndim, (float*)p_y, 2*NL, Ndim);

    // channel mix -> embed, pool
    k_mix2<<<dim3(NL/160, Bdim), 320, MIX_SMEM>>>(x, be, bp);

    k_softmax<<<BC, Ndim>>>();

    // x_new = s^T @ embed
    k_tgemm4<true><<<dim3(BC, 2, 1), 320, TG<true>::SMEM>>>(
        (const float*)p_pool, NL, Ndim, (const float*)p_embed, NL, Ndim,
        xnew, NL, Ndim);

    // t = s @ a  (B shared)
    k_tgemm4<false><<<dim3(BC, 2, 1), 320, TG<false>::SMEM>>>(
        (const float*)p_pool, NL, Ndim, a, 0, Ndim, (float*)p_t, NL, Ndim);

    // a_new = t @ s
    k_tgemm4<false><<<dim3(BC, 2, 1), 320, TG<false>::SMEM>>>(
        (const float*)p_t, NL, Ndim, (const float*)p_pool, NL, Ndim,
        anew, NL, Ndim);
}